// round 1
// baseline (speedup 1.0000x reference)
#include <cuda_runtime.h>

#define BB   4
#define CC   256
#define CHH  128
#define NN   4096

#define TILE   128
#define BK     16
#define SPITCH 132   // 128 + 4 pad (keeps float4 alignment, breaks bank conflicts)

// ---------------- scratch (device globals; no allocation allowed) ----------------
__device__ float g_theta[(size_t)BB * NN * CHH];   // [b][n][ch]
__device__ float g_phi  [(size_t)BB * NN * CHH];
__device__ float g_gv   [(size_t)BB * NN * CHH];
__device__ float g_O    [(size_t)BB * NN * CHH];   // attention output [b][i][ch]
__device__ float g_S    [(size_t)BB * NN * NN];    // scores / probs [b][j][i]  (268 MB)
__device__ float g_Zinv [BB * NN];                 // 1/Z per row j

// ---------------- fast exp (FFMA-only; valid for x <= 0, rel err ~2.4e-6) ----------
__device__ __forceinline__ float fast_exp(float x) {
    float t = fmaxf(x * 1.4426950408889634f, -120.0f);  // log2(e)*x, clamped
    float z = t + 12582912.0f;                           // round-to-nearest integer trick
    int   e = __float_as_int(z);                         // low bits hold round(t)
    float f = t - (z - 12582912.0f);                     // f in [-0.5, 0.5]
    // 2^f, degree-5 Taylor in ln2
    float p = 1.3333558e-3f;
    p = fmaf(p, f, 9.6181291e-3f);
    p = fmaf(p, f, 5.5504109e-2f);
    p = fmaf(p, f, 2.4022651e-1f);
    p = fmaf(p, f, 6.9314718e-1f);
    p = fmaf(p, f, 1.0f);
    // (e<<23) == round(t)<<23 since low 9 bits of bits(12582912.0f) are 0
    return __int_as_float((e << 23) + __float_as_int(p));
}

// ---------------- shared 8x8-micro GEMM step ----------------
__device__ __forceinline__ void gemm_step(const float* __restrict__ As,
                                          const float* __restrict__ Bs,
                                          float (&acc)[8][8], int ty, int tx) {
#pragma unroll
    for (int k = 0; k < BK; ++k) {
        float a[8], b[8];
        *(float4*)&a[0] = *(const float4*)&As[k * SPITCH + ty * 8];
        *(float4*)&a[4] = *(const float4*)&As[k * SPITCH + ty * 8 + 4];
        *(float4*)&b[0] = *(const float4*)&Bs[k * SPITCH + tx * 8];
        *(float4*)&b[4] = *(const float4*)&Bs[k * SPITCH + tx * 8 + 4];
#pragma unroll
        for (int r = 0; r < 8; ++r)
#pragma unroll
            for (int c = 0; c < 8; ++c)
                acc[r][c] = fmaf(a[r], b[c], acc[r][c]);
    }
}

// ================= K1: theta/phi/g projections =================
// out[b][n][o] = sum_c w[o][c] * x[b][c][n] + bias[o]
__global__ __launch_bounds__(256) void k1_proj(
    const float* __restrict__ x,
    const float* __restrict__ tw, const float* __restrict__ tb,
    const float* __restrict__ pw, const float* __restrict__ pb,
    const float* __restrict__ gw, const float* __restrict__ gb)
{
    __shared__ float As[BK * SPITCH];   // [k(c)][n]
    __shared__ float Bs[BK * SPITCH];   // [k(c)][o]
    const int b    = blockIdx.z;
    const int proj = blockIdx.y;
    const int n0   = blockIdx.x * TILE;
    const float* w    = proj == 0 ? tw : (proj == 1 ? pw : gw);
    const float* bias = proj == 0 ? tb : (proj == 1 ? pb : gb);
    float*       out  = proj == 0 ? g_theta : (proj == 1 ? g_phi : g_gv);

    const int tid = threadIdx.x, ty = tid >> 4, tx = tid & 15;
    const float* xb = x + (size_t)b * CC * NN;

    float acc[8][8];
#pragma unroll
    for (int r = 0; r < 8; ++r)
#pragma unroll
        for (int c = 0; c < 8; ++c) acc[r][c] = 0.f;

    for (int k0 = 0; k0 < CC; k0 += BK) {
#pragma unroll
        for (int it = 0; it < 2; ++it) {      // As: 16 x 128 from x (n contiguous)
            int idx = tid + it * 256;
            int nn4 = idx & 31, kk = idx >> 5;
            *(float4*)&As[kk * SPITCH + nn4 * 4] =
                *(const float4*)(xb + (size_t)(k0 + kk) * NN + n0 + nn4 * 4);
        }
#pragma unroll
        for (int it = 0; it < 2; ++it) {      // Bs: 16 x 128 from w (c contiguous)
            int idx = tid + it * 256;
            int kk4 = idx & 3, o = idx >> 2;
            float4 v = *(const float4*)(w + (size_t)o * CC + k0 + kk4 * 4);
            Bs[(kk4 * 4 + 0) * SPITCH + o] = v.x;
            Bs[(kk4 * 4 + 1) * SPITCH + o] = v.y;
            Bs[(kk4 * 4 + 2) * SPITCH + o] = v.z;
            Bs[(kk4 * 4 + 3) * SPITCH + o] = v.w;
        }
        __syncthreads();
        gemm_step(As, Bs, acc, ty, tx);
        __syncthreads();
    }

    float bi[8];
#pragma unroll
    for (int c = 0; c < 8; ++c) bi[c] = bias[tx * 8 + c];
    float* ob = out + (size_t)b * NN * CHH;
#pragma unroll
    for (int r = 0; r < 8; ++r) {
        int n = n0 + ty * 8 + r;
        float4 v0 = make_float4(acc[r][0] + bi[0], acc[r][1] + bi[1],
                                acc[r][2] + bi[2], acc[r][3] + bi[3]);
        float4 v1 = make_float4(acc[r][4] + bi[4], acc[r][5] + bi[5],
                                acc[r][6] + bi[6], acc[r][7] + bi[7]);
        *(float4*)&ob[(size_t)n * CHH + tx * 8]     = v0;
        *(float4*)&ob[(size_t)n * CHH + tx * 8 + 4] = v1;
    }
}

// ================= K2: S[j][i] = theta_j . phi_i =================
__global__ __launch_bounds__(256) void k2_scores()
{
    __shared__ float As[BK * SPITCH];   // [k(ch)][j]
    __shared__ float Bs[BK * SPITCH];   // [k(ch)][i]
    const int b  = blockIdx.z;
    const int j0 = blockIdx.y * TILE;
    const int i0 = blockIdx.x * TILE;
    const int tid = threadIdx.x, ty = tid >> 4, tx = tid & 15;
    const float* th = g_theta + (size_t)b * NN * CHH;
    const float* ph = g_phi   + (size_t)b * NN * CHH;

    float acc[8][8];
#pragma unroll
    for (int r = 0; r < 8; ++r)
#pragma unroll
        for (int c = 0; c < 8; ++c) acc[r][c] = 0.f;

    for (int k0 = 0; k0 < CHH; k0 += BK) {
#pragma unroll
        for (int it = 0; it < 2; ++it) {
            int idx = tid + it * 256;
            int kk4 = idx & 3, rr = idx >> 2;
            float4 va = *(const float4*)(th + (size_t)(j0 + rr) * CHH + k0 + kk4 * 4);
            As[(kk4 * 4 + 0) * SPITCH + rr] = va.x;
            As[(kk4 * 4 + 1) * SPITCH + rr] = va.y;
            As[(kk4 * 4 + 2) * SPITCH + rr] = va.z;
            As[(kk4 * 4 + 3) * SPITCH + rr] = va.w;
            float4 vb = *(const float4*)(ph + (size_t)(i0 + rr) * CHH + k0 + kk4 * 4);
            Bs[(kk4 * 4 + 0) * SPITCH + rr] = vb.x;
            Bs[(kk4 * 4 + 1) * SPITCH + rr] = vb.y;
            Bs[(kk4 * 4 + 2) * SPITCH + rr] = vb.z;
            Bs[(kk4 * 4 + 3) * SPITCH + rr] = vb.w;
        }
        __syncthreads();
        gemm_step(As, Bs, acc, ty, tx);
        __syncthreads();
    }

    float* Sb = g_S + (size_t)b * NN * NN;
#pragma unroll
    for (int r = 0; r < 8; ++r) {
        int j = j0 + ty * 8 + r;
        *(float4*)&Sb[(size_t)j * NN + i0 + tx * 8]     =
            make_float4(acc[r][0], acc[r][1], acc[r][2], acc[r][3]);
        *(float4*)&Sb[(size_t)j * NN + i0 + tx * 8 + 4] =
            make_float4(acc[r][4], acc[r][5], acc[r][6], acc[r][7]);
    }
}

// ================= K3: per-row softmax stats; S <- exp(S - m); Zinv =================
__global__ __launch_bounds__(256) void k3_softmax()
{
    const int warp = threadIdx.x >> 5, lane = threadIdx.x & 31;
    const size_t row = (size_t)blockIdx.x * 8 + warp;      // b*NN + j
    float4* S4 = (float4*)(g_S + row * NN);

    float mx = -3.0e38f;
    for (int it = lane; it < NN / 4; it += 32) {
        float4 v = S4[it];
        mx = fmaxf(mx, fmaxf(fmaxf(v.x, v.y), fmaxf(v.z, v.w)));
    }
#pragma unroll
    for (int o = 16; o; o >>= 1) mx = fmaxf(mx, __shfl_xor_sync(0xffffffffu, mx, o));

    float s = 0.f;
    for (int it = lane; it < NN / 4; it += 32) {
        float4 v = S4[it];
        v.x = fast_exp(v.x - mx);
        v.y = fast_exp(v.y - mx);
        v.z = fast_exp(v.z - mx);
        v.w = fast_exp(v.w - mx);
        s += (v.x + v.y) + (v.z + v.w);
        S4[it] = v;
    }
#pragma unroll
    for (int o = 16; o; o >>= 1) s += __shfl_xor_sync(0xffffffffu, s, o);
    if (lane == 0) g_Zinv[row] = 1.0f / s;
}

// ================= K4: O[i][c] = sum_j P[j][i] * (g[j][c] * Zinv[j]) =================
__global__ __launch_bounds__(256) void k4_av()
{
    __shared__ float As[BK * SPITCH];   // [k(j)][i]
    __shared__ float Bs[BK * SPITCH];   // [k(j)][c]
    const int b  = blockIdx.z;
    const int i0 = blockIdx.x * TILE;
    const int tid = threadIdx.x, ty = tid >> 4, tx = tid & 15;
    const float* Sb = g_S   + (size_t)b * NN * NN;
    const float* gv = g_gv  + (size_t)b * NN * CHH;
    const float* zi = g_Zinv + b * NN;

    float acc[8][8];
#pragma unroll
    for (int r = 0; r < 8; ++r)
#pragma unroll
        for (int c = 0; c < 8; ++c) acc[r][c] = 0.f;

    for (int j0 = 0; j0 < NN; j0 += BK) {
#pragma unroll
        for (int it = 0; it < 2; ++it) {
            int idx = tid + it * 256;
            int q4 = idx & 31, kk = idx >> 5;
            *(float4*)&As[kk * SPITCH + q4 * 4] =
                *(const float4*)(Sb + (size_t)(j0 + kk) * NN + i0 + q4 * 4);
            float4 v = *(const float4*)(gv + (size_t)(j0 + kk) * CHH + q4 * 4);
            float z = zi[j0 + kk];
            v.x *= z; v.y *= z; v.z *= z; v.w *= z;
            *(float4*)&Bs[kk * SPITCH + q4 * 4] = v;
        }
        __syncthreads();
        gemm_step(As, Bs, acc, ty, tx);
        __syncthreads();
    }

    float* Ob = g_O + (size_t)b * NN * CHH;
#pragma unroll
    for (int r = 0; r < 8; ++r) {
        int i = i0 + ty * 8 + r;
        *(float4*)&Ob[(size_t)i * CHH + tx * 8]     =
            make_float4(acc[r][0], acc[r][1], acc[r][2], acc[r][3]);
        *(float4*)&Ob[(size_t)i * CHH + tx * 8 + 4] =
            make_float4(acc[r][4], acc[r][5], acc[r][6], acc[r][7]);
    }
}

// ================= K5: out[o][n] = sum_c Ww[o][c]*O[n][c] + Wb[o] + x[o][n] =================
__global__ __launch_bounds__(256) void k5_out(
    const float* __restrict__ x,
    const float* __restrict__ Ww, const float* __restrict__ Wb,
    float* __restrict__ out)
{
    __shared__ float As[BK * SPITCH];   // [k(c)][o]
    __shared__ float Bs[BK * SPITCH];   // [k(c)][n]
    const int b  = blockIdx.z;
    const int o0 = blockIdx.y * TILE;
    const int n0 = blockIdx.x * TILE;
    const int tid = threadIdx.x, ty = tid >> 4, tx = tid & 15;
    const float* Ob = g_O + (size_t)b * NN * CHH;

    float acc[8][8];
#pragma unroll
    for (int r = 0; r < 8; ++r)
#pragma unroll
        for (int c = 0; c < 8; ++c) acc[r][c] = 0.f;

    for (int k0 = 0; k0 < CHH; k0 += BK) {
#pragma unroll
        for (int it = 0; it < 2; ++it) {
            int idx = tid + it * 256;
            int kk4 = idx & 3, oo = idx >> 2;
            float4 v = *(const float4*)(Ww + (size_t)(o0 + oo) * CHH + k0 + kk4 * 4);
            As[(kk4 * 4 + 0) * SPITCH + oo] = v.x;
            As[(kk4 * 4 + 1) * SPITCH + oo] = v.y;
            As[(kk4 * 4 + 2) * SPITCH + oo] = v.z;
            As[(kk4 * 4 + 3) * SPITCH + oo] = v.w;
        }
#pragma unroll
        for (int it = 0; it < 2; ++it) {
            int idx = tid + it * 256;
            int kk4 = idx & 3, nn = idx >> 2;
            float4 v = *(const float4*)(Ob + (size_t)(n0 + nn) * CHH + k0 + kk4 * 4);
            Bs[(kk4 * 4 + 0) * SPITCH + nn] = v.x;
            Bs[(kk4 * 4 + 1) * SPITCH + nn] = v.y;
            Bs[(kk4 * 4 + 2) * SPITCH + nn] = v.z;
            Bs[(kk4 * 4 + 3) * SPITCH + nn] = v.w;
        }
        __syncthreads();
        gemm_step(As, Bs, acc, ty, tx);
        __syncthreads();
    }

#pragma unroll
    for (int r = 0; r < 8; ++r) {
        int o = o0 + ty * 8 + r;
        float bb = Wb[o];
        const float* xr = x   + (size_t)b * CC * NN + (size_t)o * NN + n0 + tx * 8;
        float*       yr = out + (size_t)b * CC * NN + (size_t)o * NN + n0 + tx * 8;
        float4 x0 = *(const float4*)xr;
        float4 x1 = *(const float4*)(xr + 4);
        *(float4*)yr = make_float4(acc[r][0] + bb + x0.x, acc[r][1] + bb + x0.y,
                                   acc[r][2] + bb + x0.z, acc[r][3] + bb + x0.w);
        *(float4*)(yr + 4) = make_float4(acc[r][4] + bb + x1.x, acc[r][5] + bb + x1.y,
                                         acc[r][6] + bb + x1.z, acc[r][7] + bb + x1.w);
    }
}

// ================= launch =================
extern "C" void kernel_launch(void* const* d_in, const int* in_sizes, int n_in,
                              void* d_out, int out_size) {
    const float* x  = (const float*)d_in[0];
    const float* tw = (const float*)d_in[1];
    const float* tb = (const float*)d_in[2];
    const float* pw = (const float*)d_in[3];
    const float* pb = (const float*)d_in[4];
    const float* gw = (const float*)d_in[5];
    const float* gb = (const float*)d_in[6];
    const float* Ww = (const float*)d_in[7];
    const float* Wb = (const float*)d_in[8];
    float* out = (float*)d_out;

    k1_proj   <<<dim3(NN / TILE, 3, BB),        256>>>(x, tw, tb, pw, pb, gw, gb);
    k2_scores <<<dim3(NN / TILE, NN / TILE, BB), 256>>>();
    k3_softmax<<<dim3(BB * NN / 8),              256>>>();
    k4_av     <<<dim3(NN / TILE, 1, BB),         256>>>();
    k5_out    <<<dim3(NN / TILE, CC / TILE, BB), 256>>>(x, Ww, Wb, out);
}

// round 2
// speedup vs baseline: 1.0001x; 1.0001x over previous
#include <cuda_runtime.h>

#define BB   4
#define CC   256
#define CHH  128
#define NN   4096

#define TILE   128
#define BK     16
#define SPITCH 132   // 128 + 4 pad (keeps float4 alignment, breaks bank conflicts)

// ---------------- scratch (device globals; no allocation allowed) ----------------
__device__ float g_theta[(size_t)BB * NN * CHH];   // [b][n][ch]
__device__ float g_phi  [(size_t)BB * NN * CHH];
__device__ float g_gv   [(size_t)BB * NN * CHH];
__device__ float g_O    [(size_t)BB * NN * CHH];   // attention output [b][i][ch]
__device__ float g_S    [(size_t)BB * NN * NN];    // scores / probs [b][j][i]  (268 MB)
__device__ float g_Zinv [BB * NN];                 // 1/Z per row j

// ---------------- fast exp (FFMA-only; valid for x <= 0, rel err ~2.4e-6) ----------
__device__ __forceinline__ float fast_exp(float x) {
    float t = fmaxf(x * 1.4426950408889634f, -120.0f);  // log2(e)*x, clamped
    float z = t + 12582912.0f;                           // round-to-nearest integer trick
    int   e = __float_as_int(z);                         // low bits hold round(t)
    float f = t - (z - 12582912.0f);                     // f in [-0.5, 0.5]
    // 2^f, degree-5 Taylor in ln2
    float p = 1.3333558e-3f;
    p = fmaf(p, f, 9.6181291e-3f);
    p = fmaf(p, f, 5.5504109e-2f);
    p = fmaf(p, f, 2.4022651e-1f);
    p = fmaf(p, f, 6.9314718e-1f);
    p = fmaf(p, f, 1.0f);
    // (e<<23) == round(t)<<23 since low 9 bits of bits(12582912.0f) are 0
    return __int_as_float((e << 23) + __float_as_int(p));
}

// ---------------- shared 8x8-micro GEMM step ----------------
__device__ __forceinline__ void gemm_step(const float* __restrict__ As,
                                          const float* __restrict__ Bs,
                                          float (&acc)[8][8], int ty, int tx) {
#pragma unroll
    for (int k = 0; k < BK; ++k) {
        float a[8], b[8];
        *(float4*)&a[0] = *(const float4*)&As[k * SPITCH + ty * 8];
        *(float4*)&a[4] = *(const float4*)&As[k * SPITCH + ty * 8 + 4];
        *(float4*)&b[0] = *(const float4*)&Bs[k * SPITCH + tx * 8];
        *(float4*)&b[4] = *(const float4*)&Bs[k * SPITCH + tx * 8 + 4];
#pragma unroll
        for (int r = 0; r < 8; ++r)
#pragma unroll
            for (int c = 0; c < 8; ++c)
                acc[r][c] = fmaf(a[r], b[c], acc[r][c]);
    }
}

// ================= K1: theta/phi/g projections =================
// out[b][n][o] = sum_c w[o][c] * x[b][c][n] + bias[o]
__global__ __launch_bounds__(256) void k1_proj(
    const float* __restrict__ x,
    const float* __restrict__ tw, const float* __restrict__ tb,
    const float* __restrict__ pw, const float* __restrict__ pb,
    const float* __restrict__ gw, const float* __restrict__ gb)
{
    __shared__ float As[BK * SPITCH];   // [k(c)][n]
    __shared__ float Bs[BK * SPITCH];   // [k(c)][o]
    const int b    = blockIdx.z;
    const int proj = blockIdx.y;
    const int n0   = blockIdx.x * TILE;
    const float* w    = proj == 0 ? tw : (proj == 1 ? pw : gw);
    const float* bias = proj == 0 ? tb : (proj == 1 ? pb : gb);
    float*       out  = proj == 0 ? g_theta : (proj == 1 ? g_phi : g_gv);

    const int tid = threadIdx.x, ty = tid >> 4, tx = tid & 15;
    const float* xb = x + (size_t)b * CC * NN;

    float acc[8][8];
#pragma unroll
    for (int r = 0; r < 8; ++r)
#pragma unroll
        for (int c = 0; c < 8; ++c) acc[r][c] = 0.f;

    for (int k0 = 0; k0 < CC; k0 += BK) {
#pragma unroll
        for (int it = 0; it < 2; ++it) {      // As: 16 x 128 from x (n contiguous)
            int idx = tid + it * 256;
            int nn4 = idx & 31, kk = idx >> 5;
            *(float4*)&As[kk * SPITCH + nn4 * 4] =
                *(const float4*)(xb + (size_t)(k0 + kk) * NN + n0 + nn4 * 4);
        }
#pragma unroll
        for (int it = 0; it < 2; ++it) {      // Bs: 16 x 128 from w (c contiguous)
            int idx = tid + it * 256;
            int kk4 = idx & 3, o = idx >> 2;
            float4 v = *(const float4*)(w + (size_t)o * CC + k0 + kk4 * 4);
            Bs[(kk4 * 4 + 0) * SPITCH + o] = v.x;
            Bs[(kk4 * 4 + 1) * SPITCH + o] = v.y;
            Bs[(kk4 * 4 + 2) * SPITCH + o] = v.z;
            Bs[(kk4 * 4 + 3) * SPITCH + o] = v.w;
        }
        __syncthreads();
        gemm_step(As, Bs, acc, ty, tx);
        __syncthreads();
    }

    float bi[8];
#pragma unroll
    for (int c = 0; c < 8; ++c) bi[c] = bias[tx * 8 + c];
    float* ob = out + (size_t)b * NN * CHH;
#pragma unroll
    for (int r = 0; r < 8; ++r) {
        int n = n0 + ty * 8 + r;
        float4 v0 = make_float4(acc[r][0] + bi[0], acc[r][1] + bi[1],
                                acc[r][2] + bi[2], acc[r][3] + bi[3]);
        float4 v1 = make_float4(acc[r][4] + bi[4], acc[r][5] + bi[5],
                                acc[r][6] + bi[6], acc[r][7] + bi[7]);
        *(float4*)&ob[(size_t)n * CHH + tx * 8]     = v0;
        *(float4*)&ob[(size_t)n * CHH + tx * 8 + 4] = v1;
    }
}

// ================= K2: S[j][i] = theta_j . phi_i =================
__global__ __launch_bounds__(256) void k2_scores()
{
    __shared__ float As[BK * SPITCH];   // [k(ch)][j]
    __shared__ float Bs[BK * SPITCH];   // [k(ch)][i]
    const int b  = blockIdx.z;
    const int j0 = blockIdx.y * TILE;
    const int i0 = blockIdx.x * TILE;
    const int tid = threadIdx.x, ty = tid >> 4, tx = tid & 15;
    const float* th = g_theta + (size_t)b * NN * CHH;
    const float* ph = g_phi   + (size_t)b * NN * CHH;

    float acc[8][8];
#pragma unroll
    for (int r = 0; r < 8; ++r)
#pragma unroll
        for (int c = 0; c < 8; ++c) acc[r][c] = 0.f;

    for (int k0 = 0; k0 < CHH; k0 += BK) {
#pragma unroll
        for (int it = 0; it < 2; ++it) {
            int idx = tid + it * 256;
            int kk4 = idx & 3, rr = idx >> 2;
            float4 va = *(const float4*)(th + (size_t)(j0 + rr) * CHH + k0 + kk4 * 4);
            As[(kk4 * 4 + 0) * SPITCH + rr] = va.x;
            As[(kk4 * 4 + 1) * SPITCH + rr] = va.y;
            As[(kk4 * 4 + 2) * SPITCH + rr] = va.z;
            As[(kk4 * 4 + 3) * SPITCH + rr] = va.w;
            float4 vb = *(const float4*)(ph + (size_t)(i0 + rr) * CHH + k0 + kk4 * 4);
            Bs[(kk4 * 4 + 0) * SPITCH + rr] = vb.x;
            Bs[(kk4 * 4 + 1) * SPITCH + rr] = vb.y;
            Bs[(kk4 * 4 + 2) * SPITCH + rr] = vb.z;
            Bs[(kk4 * 4 + 3) * SPITCH + rr] = vb.w;
        }
        __syncthreads();
        gemm_step(As, Bs, acc, ty, tx);
        __syncthreads();
    }

    float* Sb = g_S + (size_t)b * NN * NN;
#pragma unroll
    for (int r = 0; r < 8; ++r) {
        int j = j0 + ty * 8 + r;
        *(float4*)&Sb[(size_t)j * NN + i0 + tx * 8]     =
            make_float4(acc[r][0], acc[r][1], acc[r][2], acc[r][3]);
        *(float4*)&Sb[(size_t)j * NN + i0 + tx * 8 + 4] =
            make_float4(acc[r][4], acc[r][5], acc[r][6], acc[r][7]);
    }
}

// ================= K3: per-row softmax stats; S <- exp(S - m); Zinv =================
__global__ __launch_bounds__(256) void k3_softmax()
{
    const int warp = threadIdx.x >> 5, lane = threadIdx.x & 31;
    const size_t row = (size_t)blockIdx.x * 8 + warp;      // b*NN + j
    float4* S4 = (float4*)(g_S + row * NN);

    float mx = -3.0e38f;
    for (int it = lane; it < NN / 4; it += 32) {
        float4 v = S4[it];
        mx = fmaxf(mx, fmaxf(fmaxf(v.x, v.y), fmaxf(v.z, v.w)));
    }
#pragma unroll
    for (int o = 16; o; o >>= 1) mx = fmaxf(mx, __shfl_xor_sync(0xffffffffu, mx, o));

    float s = 0.f;
    for (int it = lane; it < NN / 4; it += 32) {
        float4 v = S4[it];
        v.x = fast_exp(v.x - mx);
        v.y = fast_exp(v.y - mx);
        v.z = fast_exp(v.z - mx);
        v.w = fast_exp(v.w - mx);
        s += (v.x + v.y) + (v.z + v.w);
        S4[it] = v;
    }
#pragma unroll
    for (int o = 16; o; o >>= 1) s += __shfl_xor_sync(0xffffffffu, s, o);
    if (lane == 0) g_Zinv[row] = 1.0f / s;
}

// ================= K4: O[i][c] = sum_j P[j][i] * (g[j][c] * Zinv[j]) =================
__global__ __launch_bounds__(256) void k4_av()
{
    __shared__ float As[BK * SPITCH];   // [k(j)][i]
    __shared__ float Bs[BK * SPITCH];   // [k(j)][c]
    const int b  = blockIdx.z;
    const int i0 = blockIdx.x * TILE;
    const int tid = threadIdx.x, ty = tid >> 4, tx = tid & 15;
    const float* Sb = g_S   + (size_t)b * NN * NN;
    const float* gv = g_gv  + (size_t)b * NN * CHH;
    const float* zi = g_Zinv + b * NN;

    float acc[8][8];
#pragma unroll
    for (int r = 0; r < 8; ++r)
#pragma unroll
        for (int c = 0; c < 8; ++c) acc[r][c] = 0.f;

    for (int j0 = 0; j0 < NN; j0 += BK) {
#pragma unroll
        for (int it = 0; it < 2; ++it) {
            int idx = tid + it * 256;
            int q4 = idx & 31, kk = idx >> 5;
            *(float4*)&As[kk * SPITCH + q4 * 4] =
                *(const float4*)(Sb + (size_t)(j0 + kk) * NN + i0 + q4 * 4);
            float4 v = *(const float4*)(gv + (size_t)(j0 + kk) * CHH + q4 * 4);
            float z = zi[j0 + kk];
            v.x *= z; v.y *= z; v.z *= z; v.w *= z;
            *(float4*)&Bs[kk * SPITCH + q4 * 4] = v;
        }
        __syncthreads();
        gemm_step(As, Bs, acc, ty, tx);
        __syncthreads();
    }

    float* Ob = g_O + (size_t)b * NN * CHH;
#pragma unroll
    for (int r = 0; r < 8; ++r) {
        int i = i0 + ty * 8 + r;
        *(float4*)&Ob[(size_t)i * CHH + tx * 8]     =
            make_float4(acc[r][0], acc[r][1], acc[r][2], acc[r][3]);
        *(float4*)&Ob[(size_t)i * CHH + tx * 8 + 4] =
            make_float4(acc[r][4], acc[r][5], acc[r][6], acc[r][7]);
    }
}

// ================= K5: out[o][n] = sum_c Ww[o][c]*O[n][c] + Wb[o] + x[o][n] =================
__global__ __launch_bounds__(256) void k5_out(
    const float* __restrict__ x,
    const float* __restrict__ Ww, const float* __restrict__ Wb,
    float* __restrict__ out)
{
    __shared__ float As[BK * SPITCH];   // [k(c)][o]
    __shared__ float Bs[BK * SPITCH];   // [k(c)][n]
    const int b  = blockIdx.z;
    const int o0 = blockIdx.y * TILE;
    const int n0 = blockIdx.x * TILE;
    const int tid = threadIdx.x, ty = tid >> 4, tx = tid & 15;
    const float* Ob = g_O + (size_t)b * NN * CHH;

    float acc[8][8];
#pragma unroll
    for (int r = 0; r < 8; ++r)
#pragma unroll
        for (int c = 0; c < 8; ++c) acc[r][c] = 0.f;

    for (int k0 = 0; k0 < CHH; k0 += BK) {
#pragma unroll
        for (int it = 0; it < 2; ++it) {
            int idx = tid + it * 256;
            int kk4 = idx & 3, oo = idx >> 2;
            float4 v = *(const float4*)(Ww + (size_t)(o0 + oo) * CHH + k0 + kk4 * 4);
            As[(kk4 * 4 + 0) * SPITCH + oo] = v.x;
            As[(kk4 * 4 + 1) * SPITCH + oo] = v.y;
            As[(kk4 * 4 + 2) * SPITCH + oo] = v.z;
            As[(kk4 * 4 + 3) * SPITCH + oo] = v.w;
        }
#pragma unroll
        for (int it = 0; it < 2; ++it) {
            int idx = tid + it * 256;
            int kk4 = idx & 3, nn = idx >> 2;
            float4 v = *(const float4*)(Ob + (size_t)(n0 + nn) * CHH + k0 + kk4 * 4);
            Bs[(kk4 * 4 + 0) * SPITCH + nn] = v.x;
            Bs[(kk4 * 4 + 1) * SPITCH + nn] = v.y;
            Bs[(kk4 * 4 + 2) * SPITCH + nn] = v.z;
            Bs[(kk4 * 4 + 3) * SPITCH + nn] = v.w;
        }
        __syncthreads();
        gemm_step(As, Bs, acc, ty, tx);
        __syncthreads();
    }

#pragma unroll
    for (int r = 0; r < 8; ++r) {
        int o = o0 + ty * 8 + r;
        float bb = Wb[o];
        const float* xr = x   + (size_t)b * CC * NN + (size_t)o * NN + n0 + tx * 8;
        float*       yr = out + (size_t)b * CC * NN + (size_t)o * NN + n0 + tx * 8;
        float4 x0 = *(const float4*)xr;
        float4 x1 = *(const float4*)(xr + 4);
        *(float4*)yr = make_float4(acc[r][0] + bb + x0.x, acc[r][1] + bb + x0.y,
                                   acc[r][2] + bb + x0.z, acc[r][3] + bb + x0.w);
        *(float4*)(yr + 4) = make_float4(acc[r][4] + bb + x1.x, acc[r][5] + bb + x1.y,
                                         acc[r][6] + bb + x1.z, acc[r][7] + bb + x1.w);
    }
}

// ================= launch =================
extern "C" void kernel_launch(void* const* d_in, const int* in_sizes, int n_in,
                              void* d_out, int out_size) {
    const float* x  = (const float*)d_in[0];
    const float* tw = (const float*)d_in[1];
    const float* tb = (const float*)d_in[2];
    const float* pw = (const float*)d_in[3];
    const float* pb = (const float*)d_in[4];
    const float* gw = (const float*)d_in[5];
    const float* gb = (const float*)d_in[6];
    const float* Ww = (const float*)d_in[7];
    const float* Wb = (const float*)d_in[8];
    float* out = (float*)d_out;

    k1_proj   <<<dim3(NN / TILE, 3, BB),        256>>>(x, tw, tb, pw, pb, gw, gb);
    k2_scores <<<dim3(NN / TILE, NN / TILE, BB), 256>>>();
    k3_softmax<<<dim3(BB * NN / 8),              256>>>();
    k4_av     <<<dim3(NN / TILE, 1, BB),         256>>>();
    k5_out    <<<dim3(NN / TILE, CC / TILE, BB), 256>>>(x, Ww, Wb, out);
}

// round 3
// speedup vs baseline: 1.5059x; 1.5057x over previous
#include <cuda_runtime.h>

#define BB   4
#define CC   256
#define CHH  128
#define NN   4096

#define TILE   128
#define BK     16
#define SPITCH 132   // 128 + 4 pad

// ---------------- scratch ----------------
__device__ float g_theta[(size_t)BB * NN * CHH];   // [b][n][ch]
__device__ float g_phi  [(size_t)BB * NN * CHH];
__device__ float g_gv   [(size_t)BB * NN * CHH];
__device__ float g_O    [(size_t)BB * NN * CHH];   // [b][i][ch]
__device__ float g_S    [(size_t)BB * NN * NN];    // [b][j][i]
__device__ float g_Zinv [BB * NN];

// ---------------- fast exp (FFMA-only, x <= 0) ----------------
__device__ __forceinline__ float fast_exp(float x) {
    float t = fmaxf(x * 1.4426950408889634f, -120.0f);
    float z = t + 12582912.0f;
    int   e = __float_as_int(z);
    float f = t - (z - 12582912.0f);
    float p = 1.3333558e-3f;
    p = fmaf(p, f, 9.6181291e-3f);
    p = fmaf(p, f, 5.5504109e-2f);
    p = fmaf(p, f, 2.4022651e-1f);
    p = fmaf(p, f, 6.9314718e-1f);
    p = fmaf(p, f, 1.0f);
    return __int_as_float((e << 23) + __float_as_int(p));
}

// ---------------- tensor-core helpers ----------------
__device__ __forceinline__ unsigned cvt_tf32(float x) {
    unsigned r; asm("cvt.rna.tf32.f32 %0, %1;" : "=r"(r) : "f"(x)); return r;
}
__device__ __forceinline__ void mma_tf32(float* d, const unsigned* a, const unsigned* b) {
    asm volatile("mma.sync.aligned.m16n8k8.row.col.f32.tf32.tf32.f32 "
                 "{%0,%1,%2,%3}, {%4,%5,%6,%7}, {%8,%9}, {%0,%1,%2,%3};"
                 : "+f"(d[0]), "+f"(d[1]), "+f"(d[2]), "+f"(d[3])
                 : "r"(a[0]), "r"(a[1]), "r"(a[2]), "r"(a[3]),
                   "r"(b[0]), "r"(b[1]));
}
__device__ __forceinline__ void cp16(void* smem, const void* g) {
    unsigned a = (unsigned)__cvta_generic_to_shared(smem);
    asm volatile("cp.async.cg.shared.global [%0], [%1], 16;" :: "r"(a), "l"(g));
}

// ---------------- SIMT 8x8 micro GEMM (k1/k5) ----------------
__device__ __forceinline__ void gemm_step(const float* __restrict__ As,
                                          const float* __restrict__ Bs,
                                          float (&acc)[8][8], int ty, int tx) {
#pragma unroll
    for (int k = 0; k < BK; ++k) {
        float a[8], b[8];
        *(float4*)&a[0] = *(const float4*)&As[k * SPITCH + ty * 8];
        *(float4*)&a[4] = *(const float4*)&As[k * SPITCH + ty * 8 + 4];
        *(float4*)&b[0] = *(const float4*)&Bs[k * SPITCH + tx * 8];
        *(float4*)&b[4] = *(const float4*)&Bs[k * SPITCH + tx * 8 + 4];
#pragma unroll
        for (int r = 0; r < 8; ++r)
#pragma unroll
            for (int c = 0; c < 8; ++c)
                acc[r][c] = fmaf(a[r], b[c], acc[r][c]);
    }
}

// ================= K1: theta/phi/g projections (unchanged) =================
__global__ __launch_bounds__(256) void k1_proj(
    const float* __restrict__ x,
    const float* __restrict__ tw, const float* __restrict__ tb,
    const float* __restrict__ pw, const float* __restrict__ pb,
    const float* __restrict__ gw, const float* __restrict__ gb)
{
    __shared__ float As[BK * SPITCH];
    __shared__ float Bs[BK * SPITCH];
    const int b    = blockIdx.z;
    const int proj = blockIdx.y;
    const int n0   = blockIdx.x * TILE;
    const float* w    = proj == 0 ? tw : (proj == 1 ? pw : gw);
    const float* bias = proj == 0 ? tb : (proj == 1 ? pb : gb);
    float*       out  = proj == 0 ? g_theta : (proj == 1 ? g_phi : g_gv);

    const int tid = threadIdx.x, ty = tid >> 4, tx = tid & 15;
    const float* xb = x + (size_t)b * CC * NN;

    float acc[8][8] = {};
    for (int k0 = 0; k0 < CC; k0 += BK) {
#pragma unroll
        for (int it = 0; it < 2; ++it) {
            int idx = tid + it * 256;
            int nn4 = idx & 31, kk = idx >> 5;
            *(float4*)&As[kk * SPITCH + nn4 * 4] =
                *(const float4*)(xb + (size_t)(k0 + kk) * NN + n0 + nn4 * 4);
        }
#pragma unroll
        for (int it = 0; it < 2; ++it) {
            int idx = tid + it * 256;
            int kk4 = idx & 3, o = idx >> 2;
            float4 v = *(const float4*)(w + (size_t)o * CC + k0 + kk4 * 4);
            Bs[(kk4 * 4 + 0) * SPITCH + o] = v.x;
            Bs[(kk4 * 4 + 1) * SPITCH + o] = v.y;
            Bs[(kk4 * 4 + 2) * SPITCH + o] = v.z;
            Bs[(kk4 * 4 + 3) * SPITCH + o] = v.w;
        }
        __syncthreads();
        gemm_step(As, Bs, acc, ty, tx);
        __syncthreads();
    }

    float bi[8];
#pragma unroll
    for (int c = 0; c < 8; ++c) bi[c] = bias[tx * 8 + c];
    float* ob = out + (size_t)b * NN * CHH;
#pragma unroll
    for (int r = 0; r < 8; ++r) {
        int n = n0 + ty * 8 + r;
        *(float4*)&ob[(size_t)n * CHH + tx * 8] =
            make_float4(acc[r][0] + bi[0], acc[r][1] + bi[1],
                        acc[r][2] + bi[2], acc[r][3] + bi[3]);
        *(float4*)&ob[(size_t)n * CHH + tx * 8 + 4] =
            make_float4(acc[r][4] + bi[4], acc[r][5] + bi[5],
                        acc[r][6] + bi[6], acc[r][7] + bi[7]);
    }
}

// ================= K2: S = theta . phi^T  (split-TF32 x3 tensor) =================
// block tile: 128 (j) x 64 (i), BK=16; 8 warps = 4(m) x 2(n), warp tile 32x32
#define K2_PA 132
#define K2_PB 68
__global__ __launch_bounds__(256) void k2_scores_mma()
{
    __shared__ float As[BK * K2_PA];   // [k][j]
    __shared__ float Bs[BK * K2_PB];   // [k][i]
    const int b  = blockIdx.z;
    const int j0 = blockIdx.y * 128;
    const int i0 = blockIdx.x * 64;
    const int tid = threadIdx.x;
    const int warp = tid >> 5, lane = tid & 31;
    const int g = lane >> 2, t = lane & 3;
    const int wm = (warp >> 1) * 32;
    const int wn = (warp & 1) * 32;
    const float* th = g_theta + (size_t)b * NN * CHH;
    const float* ph = g_phi   + (size_t)b * NN * CHH;

    float acc[2][4][4] = {};

    for (int k0 = 0; k0 < CHH; k0 += BK) {
#pragma unroll
        for (int it = 0; it < 2; ++it) {          // As: 16 x 128 (transpose)
            int idx = tid + it * 256;
            int kk4 = idx & 3, rr = idx >> 2;
            float4 v = *(const float4*)(th + (size_t)(j0 + rr) * CHH + k0 + kk4 * 4);
            As[(kk4 * 4 + 0) * K2_PA + rr] = v.x;
            As[(kk4 * 4 + 1) * K2_PA + rr] = v.y;
            As[(kk4 * 4 + 2) * K2_PA + rr] = v.z;
            As[(kk4 * 4 + 3) * K2_PA + rr] = v.w;
        }
        {                                          // Bs: 16 x 64
            int kk4 = tid & 3, rr = tid >> 2;      // rr 0..63
            float4 v = *(const float4*)(ph + (size_t)(i0 + rr) * CHH + k0 + kk4 * 4);
            Bs[(kk4 * 4 + 0) * K2_PB + rr] = v.x;
            Bs[(kk4 * 4 + 1) * K2_PB + rr] = v.y;
            Bs[(kk4 * 4 + 2) * K2_PB + rr] = v.z;
            Bs[(kk4 * 4 + 3) * K2_PB + rr] = v.w;
        }
        __syncthreads();

#pragma unroll
        for (int ks = 0; ks < BK; ks += 8) {
            unsigned aB[2][4], aS[2][4], bB[4][2], bS[4][2];
#pragma unroll
            for (int mi = 0; mi < 2; ++mi) {
                int m = wm + mi * 16 + g;
                float f[4];
                f[0] = As[(ks + t)     * K2_PA + m];
                f[1] = As[(ks + t)     * K2_PA + m + 8];
                f[2] = As[(ks + t + 4) * K2_PA + m];
                f[3] = As[(ks + t + 4) * K2_PA + m + 8];
#pragma unroll
                for (int r = 0; r < 4; ++r) {
                    aB[mi][r] = cvt_tf32(f[r]);
                    aS[mi][r] = cvt_tf32(f[r] - __uint_as_float(aB[mi][r]));
                }
            }
#pragma unroll
            for (int ni = 0; ni < 4; ++ni) {
                int n = wn + ni * 8 + g;
                float f0 = Bs[(ks + t)     * K2_PB + n];
                float f1 = Bs[(ks + t + 4) * K2_PB + n];
                bB[ni][0] = cvt_tf32(f0);
                bS[ni][0] = cvt_tf32(f0 - __uint_as_float(bB[ni][0]));
                bB[ni][1] = cvt_tf32(f1);
                bS[ni][1] = cvt_tf32(f1 - __uint_as_float(bB[ni][1]));
            }
#pragma unroll
            for (int mi = 0; mi < 2; ++mi)
#pragma unroll
                for (int ni = 0; ni < 4; ++ni) {
                    mma_tf32(acc[mi][ni], aB[mi], bS[ni]);
                    mma_tf32(acc[mi][ni], aS[mi], bB[ni]);
                    mma_tf32(acc[mi][ni], aB[mi], bB[ni]);
                }
        }
        __syncthreads();
    }

    float* Sb = g_S + (size_t)b * NN * NN;
#pragma unroll
    for (int mi = 0; mi < 2; ++mi)
#pragma unroll
        for (int ni = 0; ni < 4; ++ni) {
            int j = j0 + wm + mi * 16 + g;
            int i = i0 + wn + ni * 8 + t * 2;
            *(float2*)&Sb[(size_t)j * NN + i] =
                make_float2(acc[mi][ni][0], acc[mi][ni][1]);
            *(float2*)&Sb[(size_t)(j + 8) * NN + i] =
                make_float2(acc[mi][ni][2], acc[mi][ni][3]);
        }
}

// ================= K3: row softmax -> exp(S-m) in place, Zinv =================
__global__ __launch_bounds__(256) void k3_softmax()
{
    const int warp = threadIdx.x >> 5, lane = threadIdx.x & 31;
    const size_t row = (size_t)blockIdx.x * 8 + warp;
    float4* S4 = (float4*)(g_S + row * NN);

    float mx = -3.0e38f;
    for (int it = lane; it < NN / 4; it += 32) {
        float4 v = S4[it];
        mx = fmaxf(mx, fmaxf(fmaxf(v.x, v.y), fmaxf(v.z, v.w)));
    }
#pragma unroll
    for (int o = 16; o; o >>= 1) mx = fmaxf(mx, __shfl_xor_sync(0xffffffffu, mx, o));

    float s = 0.f;
    for (int it = lane; it < NN / 4; it += 32) {
        float4 v = S4[it];
        v.x = fast_exp(v.x - mx);
        v.y = fast_exp(v.y - mx);
        v.z = fast_exp(v.z - mx);
        v.w = fast_exp(v.w - mx);
        s += (v.x + v.y) + (v.z + v.w);
        S4[it] = v;
    }
#pragma unroll
    for (int o = 16; o; o >>= 1) s += __shfl_xor_sync(0xffffffffu, s, o);
    if (lane == 0) g_Zinv[row] = 1.0f / s;
}

// ================= K3b: g_gv[row][:] *= Zinv[row] =================
__global__ __launch_bounds__(256) void k3b_scale_g()
{
    size_t idx = (size_t)blockIdx.x * 256 + threadIdx.x;   // float4 index
    size_t row = idx >> 5;                                  // CHH/4 = 32 float4 per row
    float z = g_Zinv[row];
    float4* p = (float4*)g_gv + idx;
    float4 v = *p;
    v.x *= z; v.y *= z; v.z *= z; v.w *= z;
    *p = v;
}

// ================= K4: O[i][c] = sum_j P[j][i] * g'[j][c]  (TF32 tensor, cp.async) ===
// block tile: 64 (i) x 128 (c), BK=16, double buffered; 8 warps = 2(m) x 4(n)
#define K4_PA 68
#define K4_PB 132
__global__ __launch_bounds__(256) void k4_av_mma()
{
    __shared__ float As[2][BK * K4_PA];   // [k(j)][i]
    __shared__ float Bs[2][BK * K4_PB];   // [k(j)][c]
    const int b  = blockIdx.y;
    const int i0 = blockIdx.x * 64;
    const int tid = threadIdx.x;
    const int warp = tid >> 5, lane = tid & 31;
    const int g = lane >> 2, t = lane & 3;
    const int wm = (warp >> 2) * 32;
    const int wn = (warp & 3) * 32;
    const float* Sb = g_S  + (size_t)b * NN * NN;
    const float* gv = g_gv + (size_t)b * NN * CHH;

    const int ar = tid >> 4, ac = (tid & 15) * 4;          // As: 1 chunk/thread
    const int b0r = tid >> 5,        b0c = (tid & 31) * 4; // Bs: 2 chunks/thread
    const int b1r = (tid + 256) >> 5, b1c = b0c;

    float acc[2][4][4] = {};

    // preload stage 0
    cp16(&As[0][ar * K4_PA + ac], Sb + (size_t)ar * NN + i0 + ac);
    cp16(&Bs[0][b0r * K4_PB + b0c], gv + (size_t)b0r * CHH + b0c);
    cp16(&Bs[0][b1r * K4_PB + b1c], gv + (size_t)b1r * CHH + b1c);
    asm volatile("cp.async.commit_group;");

#pragma unroll 1
    for (int it = 0; it < NN / BK; ++it) {
        const int s = it & 1;
        if (it + 1 < NN / BK) {
            const int j0 = (it + 1) * BK;
            cp16(&As[s ^ 1][ar * K4_PA + ac], Sb + (size_t)(j0 + ar) * NN + i0 + ac);
            cp16(&Bs[s ^ 1][b0r * K4_PB + b0c], gv + (size_t)(j0 + b0r) * CHH + b0c);
            cp16(&Bs[s ^ 1][b1r * K4_PB + b1c], gv + (size_t)(j0 + b1r) * CHH + b1c);
        }
        asm volatile("cp.async.commit_group;");
        asm volatile("cp.async.wait_group 1;");
        __syncthreads();

#pragma unroll
        for (int ks = 0; ks < BK; ks += 8) {
            unsigned af[2][4], bf[4][2];
#pragma unroll
            for (int mi = 0; mi < 2; ++mi) {
                int m = wm + mi * 16 + g;
                af[mi][0] = cvt_tf32(As[s][(ks + t)     * K4_PA + m]);
                af[mi][1] = cvt_tf32(As[s][(ks + t)     * K4_PA + m + 8]);
                af[mi][2] = cvt_tf32(As[s][(ks + t + 4) * K4_PA + m]);
                af[mi][3] = cvt_tf32(As[s][(ks + t + 4) * K4_PA + m + 8]);
            }
#pragma unroll
            for (int ni = 0; ni < 4; ++ni) {
                int n = wn + ni * 8 + g;
                bf[ni][0] = cvt_tf32(Bs[s][(ks + t)     * K4_PB + n]);
                bf[ni][1] = cvt_tf32(Bs[s][(ks + t + 4) * K4_PB + n]);
            }
#pragma unroll
            for (int mi = 0; mi < 2; ++mi)
#pragma unroll
                for (int ni = 0; ni < 4; ++ni)
                    mma_tf32(acc[mi][ni], af[mi], bf[ni]);
        }
        __syncthreads();
    }

    float* Ob = g_O + (size_t)b * NN * CHH;
#pragma unroll
    for (int mi = 0; mi < 2; ++mi)
#pragma unroll
        for (int ni = 0; ni < 4; ++ni) {
            int i = i0 + wm + mi * 16 + g;
            int c = wn + ni * 8 + t * 2;
            *(float2*)&Ob[(size_t)i * CHH + c] =
                make_float2(acc[mi][ni][0], acc[mi][ni][1]);
            *(float2*)&Ob[(size_t)(i + 8) * CHH + c] =
                make_float2(acc[mi][ni][2], acc[mi][ni][3]);
        }
}

// ================= K5: final projection + bias + residual (unchanged) =================
__global__ __launch_bounds__(256) void k5_out(
    const float* __restrict__ x,
    const float* __restrict__ Ww, const float* __restrict__ Wb,
    float* __restrict__ out)
{
    __shared__ float As[BK * SPITCH];
    __shared__ float Bs[BK * SPITCH];
    const int b  = blockIdx.z;
    const int o0 = blockIdx.y * TILE;
    const int n0 = blockIdx.x * TILE;
    const int tid = threadIdx.x, ty = tid >> 4, tx = tid & 15;
    const float* Ob = g_O + (size_t)b * NN * CHH;

    float acc[8][8] = {};
    for (int k0 = 0; k0 < CHH; k0 += BK) {
#pragma unroll
        for (int it = 0; it < 2; ++it) {
            int idx = tid + it * 256;
            int kk4 = idx & 3, oo = idx >> 2;
            float4 v = *(const float4*)(Ww + (size_t)(o0 + oo) * CHH + k0 + kk4 * 4);
            As[(kk4 * 4 + 0) * SPITCH + oo] = v.x;
            As[(kk4 * 4 + 1) * SPITCH + oo] = v.y;
            As[(kk4 * 4 + 2) * SPITCH + oo] = v.z;
            As[(kk4 * 4 + 3) * SPITCH + oo] = v.w;
        }
#pragma unroll
        for (int it = 0; it < 2; ++it) {
            int idx = tid + it * 256;
            int kk4 = idx & 3, nn = idx >> 2;
            float4 v = *(const float4*)(Ob + (size_t)(n0 + nn) * CHH + k0 + kk4 * 4);
            Bs[(kk4 * 4 + 0) * SPITCH + nn] = v.x;
            Bs[(kk4 * 4 + 1) * SPITCH + nn] = v.y;
            Bs[(kk4 * 4 + 2) * SPITCH + nn] = v.z;
            Bs[(kk4 * 4 + 3) * SPITCH + nn] = v.w;
        }
        __syncthreads();
        gemm_step(As, Bs, acc, ty, tx);
        __syncthreads();
    }

#pragma unroll
    for (int r = 0; r < 8; ++r) {
        int o = o0 + ty * 8 + r;
        float bb = Wb[o];
        const float* xr = x   + (size_t)b * CC * NN + (size_t)o * NN + n0 + tx * 8;
        float*       yr = out + (size_t)b * CC * NN + (size_t)o * NN + n0 + tx * 8;
        float4 x0 = *(const float4*)xr;
        float4 x1 = *(const float4*)(xr + 4);
        *(float4*)yr = make_float4(acc[r][0] + bb + x0.x, acc[r][1] + bb + x0.y,
                                   acc[r][2] + bb + x0.z, acc[r][3] + bb + x0.w);
        *(float4*)(yr + 4) = make_float4(acc[r][4] + bb + x1.x, acc[r][5] + bb + x1.y,
                                         acc[r][6] + bb + x1.z, acc[r][7] + bb + x1.w);
    }
}

// ================= launch =================
extern "C" void kernel_launch(void* const* d_in, const int* in_sizes, int n_in,
                              void* d_out, int out_size) {
    const float* x  = (const float*)d_in[0];
    const float* tw = (const float*)d_in[1];
    const float* tb = (const float*)d_in[2];
    const float* pw = (const float*)d_in[3];
    const float* pb = (const float*)d_in[4];
    const float* gw = (const float*)d_in[5];
    const float* gb = (const float*)d_in[6];
    const float* Ww = (const float*)d_in[7];
    const float* Wb = (const float*)d_in[8];
    float* out = (float*)d_out;

    k1_proj      <<<dim3(NN / TILE, 3, BB),         256>>>(x, tw, tb, pw, pb, gw, gb);
    k2_scores_mma<<<dim3(NN / 64, NN / 128, BB),    256>>>();
    k3_softmax   <<<dim3(BB * NN / 8),              256>>>();
    k3b_scale_g  <<<dim3(BB * NN * CHH / 4 / 256),  256>>>();
    k4_av_mma    <<<dim3(NN / 64, BB),              256>>>();
    k5_out       <<<dim3(NN / TILE, CC / TILE, BB), 256>>>(x, Ww, Wb, out);
}

// round 4
// speedup vs baseline: 1.6961x; 1.1263x over previous
#include <cuda_runtime.h>

#define BB   4
#define CC   256
#define CHH  128
#define NN   4096

#define TILE   128
#define BK     16
#define SPITCH 132   // 128 + 4 pad

// ---------------- scratch ----------------
__device__ float    g_theta[(size_t)BB * NN * CHH];   // [b][n][ch]
__device__ float    g_phi  [(size_t)BB * NN * CHH];
__device__ float    g_gv   [(size_t)BB * NN * CHH];
__device__ float    g_O    [(size_t)BB * NN * CHH];   // [b][i][ch]
__device__ float    g_S    [(size_t)BB * NN * NN];    // [b][j][i]
__device__ unsigned g_rowmax[BB * NN];                 // encoded float max per row j

// ---------------- fast exp (FFMA-only, x <= 0) ----------------
__device__ __forceinline__ float fast_exp(float x) {
    float t = fmaxf(x * 1.4426950408889634f, -120.0f);
    float z = t + 12582912.0f;
    int   e = __float_as_int(z);
    float f = t - (z - 12582912.0f);
    float p = 1.3333558e-3f;
    p = fmaf(p, f, 9.6181291e-3f);
    p = fmaf(p, f, 5.5504109e-2f);
    p = fmaf(p, f, 2.4022651e-1f);
    p = fmaf(p, f, 6.9314718e-1f);
    p = fmaf(p, f, 1.0f);
    return __int_as_float((e << 23) + __float_as_int(p));
}

// ---------------- monotonic float<->uint for atomicMax ----------------
__device__ __forceinline__ unsigned enc_f(float v) {
    unsigned b = __float_as_uint(v);
    return (b & 0x80000000u) ? ~b : (b | 0x80000000u);
}
__device__ __forceinline__ float dec_f(unsigned u) {
    return (u & 0x80000000u) ? __uint_as_float(u & 0x7fffffffu)
                             : __uint_as_float(~u);
}

// ---------------- tensor-core helpers ----------------
__device__ __forceinline__ unsigned cvt_tf32(float x) {
    unsigned r; asm("cvt.rna.tf32.f32 %0, %1;" : "=r"(r) : "f"(x)); return r;
}
__device__ __forceinline__ void mma_tf32(float* d, const unsigned* a, const unsigned* b) {
    asm volatile("mma.sync.aligned.m16n8k8.row.col.f32.tf32.tf32.f32 "
                 "{%0,%1,%2,%3}, {%4,%5,%6,%7}, {%8,%9}, {%0,%1,%2,%3};"
                 : "+f"(d[0]), "+f"(d[1]), "+f"(d[2]), "+f"(d[3])
                 : "r"(a[0]), "r"(a[1]), "r"(a[2]), "r"(a[3]),
                   "r"(b[0]), "r"(b[1]));
}
__device__ __forceinline__ void cp16(void* smem, const void* g) {
    unsigned a = (unsigned)__cvta_generic_to_shared(smem);
    asm volatile("cp.async.cg.shared.global [%0], [%1], 16;" :: "r"(a), "l"(g));
}

// ---------------- SIMT 8x8 micro GEMM (k1/k5) ----------------
__device__ __forceinline__ void gemm_step(const float* __restrict__ As,
                                          const float* __restrict__ Bs,
                                          float (&acc)[8][8], int ty, int tx) {
#pragma unroll
    for (int k = 0; k < BK; ++k) {
        float a[8], b[8];
        *(float4*)&a[0] = *(const float4*)&As[k * SPITCH + ty * 8];
        *(float4*)&a[4] = *(const float4*)&As[k * SPITCH + ty * 8 + 4];
        *(float4*)&b[0] = *(const float4*)&Bs[k * SPITCH + tx * 8];
        *(float4*)&b[4] = *(const float4*)&Bs[k * SPITCH + tx * 8 + 4];
#pragma unroll
        for (int r = 0; r < 8; ++r)
#pragma unroll
            for (int c = 0; c < 8; ++c)
                acc[r][c] = fmaf(a[r], b[c], acc[r][c]);
    }
}

// ================= K0: init rowmax =================
__global__ __launch_bounds__(256) void k0_init() {
    g_rowmax[blockIdx.x * 256 + threadIdx.x] = 0u;   // enc(-inf) lower bound
}

// ================= K1: theta/phi/g projections =================
__global__ __launch_bounds__(256) void k1_proj(
    const float* __restrict__ x,
    const float* __restrict__ tw, const float* __restrict__ tb,
    const float* __restrict__ pw, const float* __restrict__ pb,
    const float* __restrict__ gw, const float* __restrict__ gb)
{
    __shared__ float As[BK * SPITCH];
    __shared__ float Bs[BK * SPITCH];
    const int b    = blockIdx.z;
    const int proj = blockIdx.y;
    const int n0   = blockIdx.x * TILE;
    const float* w    = proj == 0 ? tw : (proj == 1 ? pw : gw);
    const float* bias = proj == 0 ? tb : (proj == 1 ? pb : gb);
    float*       out  = proj == 0 ? g_theta : (proj == 1 ? g_phi : g_gv);

    const int tid = threadIdx.x, ty = tid >> 4, tx = tid & 15;
    const float* xb = x + (size_t)b * CC * NN;

    float acc[8][8] = {};
    for (int k0 = 0; k0 < CC; k0 += BK) {
#pragma unroll
        for (int it = 0; it < 2; ++it) {
            int idx = tid + it * 256;
            int nn4 = idx & 31, kk = idx >> 5;
            *(float4*)&As[kk * SPITCH + nn4 * 4] =
                *(const float4*)(xb + (size_t)(k0 + kk) * NN + n0 + nn4 * 4);
        }
#pragma unroll
        for (int it = 0; it < 2; ++it) {
            int idx = tid + it * 256;
            int kk4 = idx & 3, o = idx >> 2;
            float4 v = *(const float4*)(w + (size_t)o * CC + k0 + kk4 * 4);
            Bs[(kk4 * 4 + 0) * SPITCH + o] = v.x;
            Bs[(kk4 * 4 + 1) * SPITCH + o] = v.y;
            Bs[(kk4 * 4 + 2) * SPITCH + o] = v.z;
            Bs[(kk4 * 4 + 3) * SPITCH + o] = v.w;
        }
        __syncthreads();
        gemm_step(As, Bs, acc, ty, tx);
        __syncthreads();
    }

    float bi[8];
#pragma unroll
    for (int c = 0; c < 8; ++c) bi[c] = bias[tx * 8 + c];
    float* ob = out + (size_t)b * NN * CHH;
#pragma unroll
    for (int r = 0; r < 8; ++r) {
        int n = n0 + ty * 8 + r;
        *(float4*)&ob[(size_t)n * CHH + tx * 8] =
            make_float4(acc[r][0] + bi[0], acc[r][1] + bi[1],
                        acc[r][2] + bi[2], acc[r][3] + bi[3]);
        *(float4*)&ob[(size_t)n * CHH + tx * 8 + 4] =
            make_float4(acc[r][4] + bi[4], acc[r][5] + bi[5],
                        acc[r][6] + bi[6], acc[r][7] + bi[7]);
    }
}

// ================= K2: S = theta . phi^T (split-TF32 x3, cp.async, fused rowmax) ===
// tile 128(j) x 128(i); 8 warps = 2(m:64) x 4(n:32); smem [row][k] pitch 20
#define K2P 20
__global__ __launch_bounds__(256) void k2_scores_mma()
{
    __shared__ float As[2][128 * K2P];
    __shared__ float Bs[2][128 * K2P];
    const int b  = blockIdx.z;
    const int j0 = blockIdx.y * 128;
    const int i0 = blockIdx.x * 128;
    const int tid = threadIdx.x;
    const int warp = tid >> 5, lane = tid & 31;
    const int g = lane >> 2, t = lane & 3;
    const int wm = (warp >> 2) * 64;
    const int wn = (warp & 3) * 32;
    const float* th = g_theta + (size_t)b * NN * CHH + (size_t)j0 * CHH;
    const float* ph = g_phi   + (size_t)b * NN * CHH + (size_t)i0 * CHH;

    float acc[4][4][4] = {};

    // loader: 128 rows x 16 k-floats per operand; 512 16B-chunks each
    const int lr = tid >> 1, lc = (tid & 1) * 8;   // 2 chunks/thread/operand, rows 0..127
    // chunk layout: thread covers row lr, k-bytes [lc, lc+8) -> two cp16 each? use 4-chunk scheme:
    // simpler: c in {tid, tid+256}: row=c>>2, kc=(c&3)*4
#define K2_LOAD(st, k0)                                                      \
    {                                                                        \
        _Pragma("unroll")                                                    \
        for (int c = tid; c < 512; c += 256) {                               \
            int row = c >> 2, kc = (c & 3) * 4;                              \
            cp16(&As[st][row * K2P + kc], th + (size_t)row * CHH + (k0) + kc); \
            cp16(&Bs[st][row * K2P + kc], ph + (size_t)row * CHH + (k0) + kc); \
        }                                                                    \
    }

    K2_LOAD(0, 0);
    asm volatile("cp.async.commit_group;");

#pragma unroll 1
    for (int it = 0; it < CHH / BK; ++it) {
        const int s = it & 1;
        if (it + 1 < CHH / BK) K2_LOAD(s ^ 1, (it + 1) * BK);
        asm volatile("cp.async.commit_group;");
        asm volatile("cp.async.wait_group 1;");
        __syncthreads();

#pragma unroll
        for (int ks = 0; ks < BK; ks += 8) {
            unsigned aB[4][4], aS[4][4], bB[4][2], bS[4][2];
#pragma unroll
            for (int mi = 0; mi < 4; ++mi) {
                int m = wm + mi * 16 + g;
                float f0 = As[s][m * K2P + ks + t];
                float f1 = As[s][(m + 8) * K2P + ks + t];
                float f2 = As[s][m * K2P + ks + t + 4];
                float f3 = As[s][(m + 8) * K2P + ks + t + 4];
                aB[mi][0] = cvt_tf32(f0); aS[mi][0] = cvt_tf32(f0 - __uint_as_float(aB[mi][0]));
                aB[mi][1] = cvt_tf32(f1); aS[mi][1] = cvt_tf32(f1 - __uint_as_float(aB[mi][1]));
                aB[mi][2] = cvt_tf32(f2); aS[mi][2] = cvt_tf32(f2 - __uint_as_float(aB[mi][2]));
                aB[mi][3] = cvt_tf32(f3); aS[mi][3] = cvt_tf32(f3 - __uint_as_float(aB[mi][3]));
            }
#pragma unroll
            for (int ni = 0; ni < 4; ++ni) {
                int n = wn + ni * 8 + g;
                float f0 = Bs[s][n * K2P + ks + t];
                float f1 = Bs[s][n * K2P + ks + t + 4];
                bB[ni][0] = cvt_tf32(f0); bS[ni][0] = cvt_tf32(f0 - __uint_as_float(bB[ni][0]));
                bB[ni][1] = cvt_tf32(f1); bS[ni][1] = cvt_tf32(f1 - __uint_as_float(bB[ni][1]));
            }
#pragma unroll
            for (int mi = 0; mi < 4; ++mi)
#pragma unroll
                for (int ni = 0; ni < 4; ++ni) {
                    mma_tf32(acc[mi][ni], aB[mi], bS[ni]);
                    mma_tf32(acc[mi][ni], aS[mi], bB[ni]);
                    mma_tf32(acc[mi][ni], aB[mi], bB[ni]);
                }
        }
        __syncthreads();
    }

    // epilogue: store S tile + fused per-row max -> atomicMax
    float* Sb = g_S + (size_t)b * NN * NN;
#pragma unroll
    for (int mi = 0; mi < 4; ++mi) {
        int j = j0 + wm + mi * 16 + g;
        float r0 = -3.0e38f, r1 = -3.0e38f;
#pragma unroll
        for (int ni = 0; ni < 4; ++ni) {
            int i = i0 + wn + ni * 8 + t * 2;
            *(float2*)&Sb[(size_t)j * NN + i] =
                make_float2(acc[mi][ni][0], acc[mi][ni][1]);
            *(float2*)&Sb[(size_t)(j + 8) * NN + i] =
                make_float2(acc[mi][ni][2], acc[mi][ni][3]);
            r0 = fmaxf(r0, fmaxf(acc[mi][ni][0], acc[mi][ni][1]));
            r1 = fmaxf(r1, fmaxf(acc[mi][ni][2], acc[mi][ni][3]));
        }
        r0 = fmaxf(r0, __shfl_xor_sync(0xffffffffu, r0, 1));
        r0 = fmaxf(r0, __shfl_xor_sync(0xffffffffu, r0, 2));
        r1 = fmaxf(r1, __shfl_xor_sync(0xffffffffu, r1, 1));
        r1 = fmaxf(r1, __shfl_xor_sync(0xffffffffu, r1, 2));
        if (t == 0) {
            atomicMax(&g_rowmax[b * NN + j],     enc_f(r0));
            atomicMax(&g_rowmax[b * NN + j + 8], enc_f(r1));
        }
    }
}

// ================= K3: single-pass exp(S-m), Z, and fold 1/Z into g =================
__global__ __launch_bounds__(256) void k3_softmax()
{
    const int warp = threadIdx.x >> 5, lane = threadIdx.x & 31;
    const size_t row = (size_t)blockIdx.x * 8 + warp;     // b*NN + j
    const float mx = dec_f(g_rowmax[row]);
    float4* S4 = (float4*)(g_S + row * NN);

    float s = 0.f;
#pragma unroll 4
    for (int it = lane; it < NN / 4; it += 32) {
        float4 v = S4[it];
        v.x = fast_exp(v.x - mx);
        v.y = fast_exp(v.y - mx);
        v.z = fast_exp(v.z - mx);
        v.w = fast_exp(v.w - mx);
        s += (v.x + v.y) + (v.z + v.w);
        S4[it] = v;
    }
#pragma unroll
    for (int o = 16; o; o >>= 1) s += __shfl_xor_sync(0xffffffffu, s, o);
    const float z = 1.0f / s;

    // fold 1/Z_j into g[:, j]  (g_gv row = row, 128 floats = 32 float4)
    float4* gv4 = (float4*)(g_gv + row * CHH);
    float4 v = gv4[lane];
    v.x *= z; v.y *= z; v.z *= z; v.w *= z;
    gv4[lane] = v;
}

// ================= K4: O[i][c] = sum_j P[j][i] * g'[j][c]  (TF32, 3-stage cp.async) ===
#define K4_PA 68
#define K4_PB 132
__global__ __launch_bounds__(256) void k4_av_mma()
{
    __shared__ float As[3][BK * K4_PA];   // [k(j)][i]
    __shared__ float Bs[3][BK * K4_PB];   // [k(j)][c]
    const int b  = blockIdx.y;
    const int i0 = blockIdx.x * 64;
    const int tid = threadIdx.x;
    const int warp = tid >> 5, lane = tid & 31;
    const int g = lane >> 2, t = lane & 3;
    const int wm = (warp >> 2) * 32;
    const int wn = (warp & 3) * 32;
    const float* Sb = g_S  + (size_t)b * NN * NN;
    const float* gv = g_gv + (size_t)b * NN * CHH;

    const int ar = tid >> 4, ac = (tid & 15) * 4;
    const int b0r = tid >> 5,         b0c = (tid & 31) * 4;
    const int b1r = (tid + 256) >> 5, b1c = b0c;

    float acc[2][4][4] = {};

#define K4_LOAD(st, j0)                                                          \
    {                                                                            \
        cp16(&As[st][ar * K4_PA + ac],   Sb + (size_t)((j0) + ar) * NN + i0 + ac);  \
        cp16(&Bs[st][b0r * K4_PB + b0c], gv + (size_t)((j0) + b0r) * CHH + b0c);    \
        cp16(&Bs[st][b1r * K4_PB + b1c], gv + (size_t)((j0) + b1r) * CHH + b1c);    \
    }

    K4_LOAD(0, 0);
    asm volatile("cp.async.commit_group;");
    K4_LOAD(1, BK);
    asm volatile("cp.async.commit_group;");

    int s = 0;
#pragma unroll 1
    for (int it = 0; it < NN / BK; ++it) {
        asm volatile("cp.async.wait_group 1;");
        __syncthreads();

#pragma unroll
        for (int ks = 0; ks < BK; ks += 8) {
            unsigned af[2][4], bf[4][2];
#pragma unroll
            for (int mi = 0; mi < 2; ++mi) {
                int m = wm + mi * 16 + g;
                af[mi][0] = cvt_tf32(As[s][(ks + t)     * K4_PA + m]);
                af[mi][1] = cvt_tf32(As[s][(ks + t)     * K4_PA + m + 8]);
                af[mi][2] = cvt_tf32(As[s][(ks + t + 4) * K4_PA + m]);
                af[mi][3] = cvt_tf32(As[s][(ks + t + 4) * K4_PA + m + 8]);
            }
#pragma unroll
            for (int ni = 0; ni < 4; ++ni) {
                int n = wn + ni * 8 + g;
                bf[ni][0] = cvt_tf32(Bs[s][(ks + t)     * K4_PB + n]);
                bf[ni][1] = cvt_tf32(Bs[s][(ks + t + 4) * K4_PB + n]);
            }
#pragma unroll
            for (int mi = 0; mi < 2; ++mi)
#pragma unroll
                for (int ni = 0; ni < 4; ++ni)
                    mma_tf32(acc[mi][ni], af[mi], bf[ni]);
        }
        __syncthreads();   // all warps done with stage s before it is refilled

        if (it + 2 < NN / BK) {
            int st = s;    // stage (it+2)%3 == current s slot after rotation below? no:
            // load into the buffer 2 ahead: (it+2)%3. Since s == it%3, (it+2)%3 == (s+2)%3.
            st = s + 2; if (st >= 3) st -= 3;
            K4_LOAD(st, (it + 2) * BK);
        }
        asm volatile("cp.async.commit_group;");

        if (++s == 3) s = 0;
    }

    float* Ob = g_O + (size_t)b * NN * CHH;
#pragma unroll
    for (int mi = 0; mi < 2; ++mi)
#pragma unroll
        for (int ni = 0; ni < 4; ++ni) {
            int i = i0 + wm + mi * 16 + g;
            int c = wn + ni * 8 + t * 2;
            *(float2*)&Ob[(size_t)i * CHH + c] =
                make_float2(acc[mi][ni][0], acc[mi][ni][1]);
            *(float2*)&Ob[(size_t)(i + 8) * CHH + c] =
                make_float2(acc[mi][ni][2], acc[mi][ni][3]);
        }
}

// ================= K5: final projection + bias + residual =================
__global__ __launch_bounds__(256) void k5_out(
    const float* __restrict__ x,
    const float* __restrict__ Ww, const float* __restrict__ Wb,
    float* __restrict__ out)
{
    __shared__ float As[BK * SPITCH];
    __shared__ float Bs[BK * SPITCH];
    const int b  = blockIdx.z;
    const int o0 = blockIdx.y * TILE;
    const int n0 = blockIdx.x * TILE;
    const int tid = threadIdx.x, ty = tid >> 4, tx = tid & 15;
    const float* Ob = g_O + (size_t)b * NN * CHH;

    float acc[8][8] = {};
    for (int k0 = 0; k0 < CHH; k0 += BK) {
#pragma unroll
        for (int it = 0; it < 2; ++it) {
            int idx = tid + it * 256;
            int kk4 = idx & 3, oo = idx >> 2;
            float4 v = *(const float4*)(Ww + (size_t)(o0 + oo) * CHH + k0 + kk4 * 4);
            As[(kk4 * 4 + 0) * SPITCH + oo] = v.x;
            As[(kk4 * 4 + 1) * SPITCH + oo] = v.y;
            As[(kk4 * 4 + 2) * SPITCH + oo] = v.z;
            As[(kk4 * 4 + 3) * SPITCH + oo] = v.w;
        }
#pragma unroll
        for (int it = 0; it < 2; ++it) {
            int idx = tid + it * 256;
            int kk4 = idx & 3, nn = idx >> 2;
            float4 v = *(const float4*)(Ob + (size_t)(n0 + nn) * CHH + k0 + kk4 * 4);
            Bs[(kk4 * 4 + 0) * SPITCH + nn] = v.x;
            Bs[(kk4 * 4 + 1) * SPITCH + nn] = v.y;
            Bs[(kk4 * 4 + 2) * SPITCH + nn] = v.z;
            Bs[(kk4 * 4 + 3) * SPITCH + nn] = v.w;
        }
        __syncthreads();
        gemm_step(As, Bs, acc, ty, tx);
        __syncthreads();
    }

#pragma unroll
    for (int r = 0; r < 8; ++r) {
        int o = o0 + ty * 8 + r;
        float bb = Wb[o];
        const float* xr = x   + (size_t)b * CC * NN + (size_t)o * NN + n0 + tx * 8;
        float*       yr = out + (size_t)b * CC * NN + (size_t)o * NN + n0 + tx * 8;
        float4 x0 = *(const float4*)xr;
        float4 x1 = *(const float4*)(xr + 4);
        *(float4*)yr = make_float4(acc[r][0] + bb + x0.x, acc[r][1] + bb + x0.y,
                                   acc[r][2] + bb + x0.z, acc[r][3] + bb + x0.w);
        *(float4*)(yr + 4) = make_float4(acc[r][4] + bb + x1.x, acc[r][5] + bb + x1.y,
                                         acc[r][6] + bb + x1.z, acc[r][7] + bb + x1.w);
    }
}

// ================= launch =================
extern "C" void kernel_launch(void* const* d_in, const int* in_sizes, int n_in,
                              void* d_out, int out_size) {
    const float* x  = (const float*)d_in[0];
    const float* tw = (const float*)d_in[1];
    const float* tb = (const float*)d_in[2];
    const float* pw = (const float*)d_in[3];
    const float* pb = (const float*)d_in[4];
    const float* gw = (const float*)d_in[5];
    const float* gb = (const float*)d_in[6];
    const float* Ww = (const float*)d_in[7];
    const float* Wb = (const float*)d_in[8];
    float* out = (float*)d_out;

    k0_init      <<<dim3(BB * NN / 256),            256>>>();
    k1_proj      <<<dim3(NN / TILE, 3, BB),         256>>>(x, tw, tb, pw, pb, gw, gb);
    k2_scores_mma<<<dim3(NN / 128, NN / 128, BB),   256>>>();
    k3_softmax   <<<dim3(BB * NN / 8),              256>>>();
    k4_av_mma    <<<dim3(NN / 64, BB),              256>>>();
    k5_out       <<<dim3(NN / TILE, CC / TILE, BB), 256>>>(x, Ww, Wb, out);
}

// round 5
// speedup vs baseline: 1.9937x; 1.1754x over previous
#include <cuda_runtime.h>
#include <cuda_bf16.h>

#define BB   4
#define CC   256
#define CHH  128
#define NN   4096

#define TILE   128
#define BK     16
#define SPITCH 132   // 128 + 4 pad

// ---------------- scratch ----------------
__device__ float    g_gv   [(size_t)BB * NN * CHH];   // g (Zinv-folded, tf32-rounded by k3)
__device__ float    g_O    [(size_t)BB * NN * CHH];   // [b][i][ch]
__device__ float    g_S    [(size_t)BB * NN * NN];    // [b][j][i]
__device__ unsigned g_rowmax[BB * NN];
// split-bf16 theta/phi (big + residual), written by k1, consumed by k2
__device__ __nv_bfloat16 g_thB[(size_t)BB * NN * CHH];
__device__ __nv_bfloat16 g_thS[(size_t)BB * NN * CHH];
__device__ __nv_bfloat16 g_phB[(size_t)BB * NN * CHH];
__device__ __nv_bfloat16 g_phS[(size_t)BB * NN * CHH];

// ---------------- fast exp (FFMA-only, x <= 0) ----------------
__device__ __forceinline__ float fast_exp(float x) {
    float t = fmaxf(x * 1.4426950408889634f, -120.0f);
    float z = t + 12582912.0f;
    int   e = __float_as_int(z);
    float f = t - (z - 12582912.0f);
    float p = 1.3333558e-3f;
    p = fmaf(p, f, 9.6181291e-3f);
    p = fmaf(p, f, 5.5504109e-2f);
    p = fmaf(p, f, 2.4022651e-1f);
    p = fmaf(p, f, 6.9314718e-1f);
    p = fmaf(p, f, 1.0f);
    return __int_as_float((e << 23) + __float_as_int(p));
}

// ---------------- monotonic float<->uint for atomicMax ----------------
__device__ __forceinline__ unsigned enc_f(float v) {
    unsigned b = __float_as_uint(v);
    return (b & 0x80000000u) ? ~b : (b | 0x80000000u);
}
__device__ __forceinline__ float dec_f(unsigned u) {
    return (u & 0x80000000u) ? __uint_as_float(u & 0x7fffffffu)
                             : __uint_as_float(~u);
}

// ---------------- tensor-core helpers ----------------
__device__ __forceinline__ unsigned cvt_tf32(float x) {
    unsigned r; asm("cvt.rna.tf32.f32 %0, %1;" : "=r"(r) : "f"(x)); return r;
}
__device__ __forceinline__ float tf32r(float x) {
    return __uint_as_float(cvt_tf32(x));
}
__device__ __forceinline__ void mma_tf32(float* d, const unsigned* a, const unsigned* b) {
    asm volatile("mma.sync.aligned.m16n8k8.row.col.f32.tf32.tf32.f32 "
                 "{%0,%1,%2,%3}, {%4,%5,%6,%7}, {%8,%9}, {%0,%1,%2,%3};"
                 : "+f"(d[0]), "+f"(d[1]), "+f"(d[2]), "+f"(d[3])
                 : "r"(a[0]), "r"(a[1]), "r"(a[2]), "r"(a[3]),
                   "r"(b[0]), "r"(b[1]));
}
__device__ __forceinline__ void mma_bf16(float* d, const unsigned* a, const unsigned* b) {
    asm volatile("mma.sync.aligned.m16n8k16.row.col.f32.bf16.bf16.f32 "
                 "{%0,%1,%2,%3}, {%4,%5,%6,%7}, {%8,%9}, {%0,%1,%2,%3};"
                 : "+f"(d[0]), "+f"(d[1]), "+f"(d[2]), "+f"(d[3])
                 : "r"(a[0]), "r"(a[1]), "r"(a[2]), "r"(a[3]),
                   "r"(b[0]), "r"(b[1]));
}
__device__ __forceinline__ void cp16(void* smem, const void* g) {
    unsigned a = (unsigned)__cvta_generic_to_shared(smem);
    asm volatile("cp.async.cg.shared.global [%0], [%1], 16;" :: "r"(a), "l"(g));
}
// split a float2 into packed bf16x2 (big) + packed bf16x2 (residual)
__device__ __forceinline__ void split2(float v0, float v1, unsigned& big, unsigned& sml) {
    asm("cvt.rn.bf16x2.f32 %0, %1, %2;" : "=r"(big) : "f"(v1), "f"(v0));
    float b0 = __uint_as_float(big << 16);
    float b1 = __uint_as_float(big & 0xffff0000u);
    float r0 = v0 - b0, r1 = v1 - b1;
    asm("cvt.rn.bf16x2.f32 %0, %1, %2;" : "=r"(sml) : "f"(r1), "f"(r0));
}

// ---------------- SIMT 8x8 micro GEMM (k1/k5) ----------------
__device__ __forceinline__ void gemm_step(const float* __restrict__ As,
                                          const float* __restrict__ Bs,
                                          float (&acc)[8][8], int ty, int tx) {
#pragma unroll
    for (int k = 0; k < BK; ++k) {
        float a[8], b[8];
        *(float4*)&a[0] = *(const float4*)&As[k * SPITCH + ty * 8];
        *(float4*)&a[4] = *(const float4*)&As[k * SPITCH + ty * 8 + 4];
        *(float4*)&b[0] = *(const float4*)&Bs[k * SPITCH + tx * 8];
        *(float4*)&b[4] = *(const float4*)&Bs[k * SPITCH + tx * 8 + 4];
#pragma unroll
        for (int r = 0; r < 8; ++r)
#pragma unroll
            for (int c = 0; c < 8; ++c)
                acc[r][c] = fmaf(a[r], b[c], acc[r][c]);
    }
}

// ================= K0: init rowmax =================
__global__ __launch_bounds__(256) void k0_init() {
    g_rowmax[blockIdx.x * 256 + threadIdx.x] = 0u;
}

// ================= K1: theta/phi/g projections =================
// theta/phi written as split bf16 pairs; g written fp32
__global__ __launch_bounds__(256) void k1_proj(
    const float* __restrict__ x,
    const float* __restrict__ tw, const float* __restrict__ tb,
    const float* __restrict__ pw, const float* __restrict__ pb,
    const float* __restrict__ gw, const float* __restrict__ gb)
{
    __shared__ float As[BK * SPITCH];
    __shared__ float Bs[BK * SPITCH];
    const int b    = blockIdx.z;
    const int proj = blockIdx.y;
    const int n0   = blockIdx.x * TILE;
    const float* w    = proj == 0 ? tw : (proj == 1 ? pw : gw);
    const float* bias = proj == 0 ? tb : (proj == 1 ? pb : gb);

    const int tid = threadIdx.x, ty = tid >> 4, tx = tid & 15;
    const float* xb = x + (size_t)b * CC * NN;

    float acc[8][8] = {};
    for (int k0 = 0; k0 < CC; k0 += BK) {
#pragma unroll
        for (int it = 0; it < 2; ++it) {
            int idx = tid + it * 256;
            int nn4 = idx & 31, kk = idx >> 5;
            *(float4*)&As[kk * SPITCH + nn4 * 4] =
                *(const float4*)(xb + (size_t)(k0 + kk) * NN + n0 + nn4 * 4);
        }
#pragma unroll
        for (int it = 0; it < 2; ++it) {
            int idx = tid + it * 256;
            int kk4 = idx & 3, o = idx >> 2;
            float4 v = *(const float4*)(w + (size_t)o * CC + k0 + kk4 * 4);
            Bs[(kk4 * 4 + 0) * SPITCH + o] = v.x;
            Bs[(kk4 * 4 + 1) * SPITCH + o] = v.y;
            Bs[(kk4 * 4 + 2) * SPITCH + o] = v.z;
            Bs[(kk4 * 4 + 3) * SPITCH + o] = v.w;
        }
        __syncthreads();
        gemm_step(As, Bs, acc, ty, tx);
        __syncthreads();
    }

    float bi[8];
#pragma unroll
    for (int c = 0; c < 8; ++c) bi[c] = bias[tx * 8 + c];

    if (proj < 2) {
        __nv_bfloat16* outB = proj == 0 ? g_thB : g_phB;
        __nv_bfloat16* outS = proj == 0 ? g_thS : g_phS;
        size_t base = (size_t)b * NN * CHH;
#pragma unroll
        for (int r = 0; r < 8; ++r) {
            int n = n0 + ty * 8 + r;
            unsigned pb4[4], ps4[4];
#pragma unroll
            for (int c = 0; c < 4; ++c)
                split2(acc[r][2 * c] + bi[2 * c], acc[r][2 * c + 1] + bi[2 * c + 1],
                       pb4[c], ps4[c]);
            *(uint4*)&outB[base + (size_t)n * CHH + tx * 8] =
                make_uint4(pb4[0], pb4[1], pb4[2], pb4[3]);
            *(uint4*)&outS[base + (size_t)n * CHH + tx * 8] =
                make_uint4(ps4[0], ps4[1], ps4[2], ps4[3]);
        }
    } else {
        float* ob = g_gv + (size_t)b * NN * CHH;
#pragma unroll
        for (int r = 0; r < 8; ++r) {
            int n = n0 + ty * 8 + r;
            *(float4*)&ob[(size_t)n * CHH + tx * 8] =
                make_float4(acc[r][0] + bi[0], acc[r][1] + bi[1],
                            acc[r][2] + bi[2], acc[r][3] + bi[3]);
            *(float4*)&ob[(size_t)n * CHH + tx * 8 + 4] =
                make_float4(acc[r][4] + bi[4], acc[r][5] + bi[5],
                            acc[r][6] + bi[6], acc[r][7] + bi[7]);
        }
    }
}

// ================= K2: S = theta . phi^T (split-bf16 x3, cp.async, fused rowmax) ===
// tile 128(j) x 128(i); 8 warps = 2(m:64) x 4(n:32); smem bf16 [row][k] pitch 24
#define K2P 24
__global__ __launch_bounds__(256) void k2_scores_mma()
{
    __shared__ __align__(16) __nv_bfloat16 sm[2][4][128 * K2P];  // thB, thS, phB, phS
    const int b  = blockIdx.z;
    const int j0 = blockIdx.y * 128;
    const int i0 = blockIdx.x * 128;
    const int tid = threadIdx.x;
    const int warp = tid >> 5, lane = tid & 31;
    const int g = lane >> 2, t = lane & 3;
    const int wm = (warp >> 2) * 64;
    const int wn = (warp & 3) * 32;
    const size_t baseJ = (size_t)b * NN * CHH + (size_t)j0 * CHH;
    const size_t baseI = (size_t)b * NN * CHH + (size_t)i0 * CHH;
    const __nv_bfloat16* thB = g_thB + baseJ;
    const __nv_bfloat16* thS = g_thS + baseJ;
    const __nv_bfloat16* phB = g_phB + baseI;
    const __nv_bfloat16* phS = g_phS + baseI;

    float acc[4][4][4] = {};

    const int lrow = tid >> 1, lkc = (tid & 1) * 8;
#define K2_LOAD(st, k0)                                                        \
    {                                                                          \
        cp16(&sm[st][0][lrow * K2P + lkc], thB + (size_t)lrow * CHH + (k0) + lkc); \
        cp16(&sm[st][1][lrow * K2P + lkc], thS + (size_t)lrow * CHH + (k0) + lkc); \
        cp16(&sm[st][2][lrow * K2P + lkc], phB + (size_t)lrow * CHH + (k0) + lkc); \
        cp16(&sm[st][3][lrow * K2P + lkc], phS + (size_t)lrow * CHH + (k0) + lkc); \
    }

    K2_LOAD(0, 0);
    asm volatile("cp.async.commit_group;");

#pragma unroll 1
    for (int it = 0; it < CHH / BK; ++it) {
        const int s = it & 1;
        if (it + 1 < CHH / BK) K2_LOAD(s ^ 1, (it + 1) * BK);
        asm volatile("cp.async.commit_group;");
        asm volatile("cp.async.wait_group 1;");
        __syncthreads();

        const __nv_bfloat16* AB = sm[s][0];
        const __nv_bfloat16* AS = sm[s][1];
        const __nv_bfloat16* PB = sm[s][2];
        const __nv_bfloat16* PS = sm[s][3];

        unsigned aB[4][4], aS[4][4], bB[4][2], bS[4][2];
#pragma unroll
        for (int mi = 0; mi < 4; ++mi) {
            int m = wm + mi * 16 + g;
            aB[mi][0] = *(const unsigned*)&AB[m * K2P + 2 * t];
            aB[mi][1] = *(const unsigned*)&AB[(m + 8) * K2P + 2 * t];
            aB[mi][2] = *(const unsigned*)&AB[m * K2P + 2 * t + 8];
            aB[mi][3] = *(const unsigned*)&AB[(m + 8) * K2P + 2 * t + 8];
            aS[mi][0] = *(const unsigned*)&AS[m * K2P + 2 * t];
            aS[mi][1] = *(const unsigned*)&AS[(m + 8) * K2P + 2 * t];
            aS[mi][2] = *(const unsigned*)&AS[m * K2P + 2 * t + 8];
            aS[mi][3] = *(const unsigned*)&AS[(m + 8) * K2P + 2 * t + 8];
        }
#pragma unroll
        for (int ni = 0; ni < 4; ++ni) {
            int n = wn + ni * 8 + g;
            bB[ni][0] = *(const unsigned*)&PB[n * K2P + 2 * t];
            bB[ni][1] = *(const unsigned*)&PB[n * K2P + 2 * t + 8];
            bS[ni][0] = *(const unsigned*)&PS[n * K2P + 2 * t];
            bS[ni][1] = *(const unsigned*)&PS[n * K2P + 2 * t + 8];
        }
#pragma unroll
        for (int mi = 0; mi < 4; ++mi)
#pragma unroll
            for (int ni = 0; ni < 4; ++ni) {
                mma_bf16(acc[mi][ni], aB[mi], bS[ni]);
                mma_bf16(acc[mi][ni], aS[mi], bB[ni]);
                mma_bf16(acc[mi][ni], aB[mi], bB[ni]);
            }
        __syncthreads();
    }

    // epilogue: store S tile + fused per-row max -> atomicMax
    float* Sb = g_S + (size_t)b * NN * NN;
#pragma unroll
    for (int mi = 0; mi < 4; ++mi) {
        int j = j0 + wm + mi * 16 + g;
        float r0 = -3.0e38f, r1 = -3.0e38f;
#pragma unroll
        for (int ni = 0; ni < 4; ++ni) {
            int i = i0 + wn + ni * 8 + t * 2;
            *(float2*)&Sb[(size_t)j * NN + i] =
                make_float2(acc[mi][ni][0], acc[mi][ni][1]);
            *(float2*)&Sb[(size_t)(j + 8) * NN + i] =
                make_float2(acc[mi][ni][2], acc[mi][ni][3]);
            r0 = fmaxf(r0, fmaxf(acc[mi][ni][0], acc[mi][ni][1]));
            r1 = fmaxf(r1, fmaxf(acc[mi][ni][2], acc[mi][ni][3]));
        }
        r0 = fmaxf(r0, __shfl_xor_sync(0xffffffffu, r0, 1));
        r0 = fmaxf(r0, __shfl_xor_sync(0xffffffffu, r0, 2));
        r1 = fmaxf(r1, __shfl_xor_sync(0xffffffffu, r1, 1));
        r1 = fmaxf(r1, __shfl_xor_sync(0xffffffffu, r1, 2));
        if (t == 0) {
            atomicMax(&g_rowmax[b * NN + j],     enc_f(r0));
            atomicMax(&g_rowmax[b * NN + j + 8], enc_f(r1));
        }
    }
}

// ================= K3: single-pass exp(S-m) [tf32-rounded], Z, fold 1/Z into g =====
__global__ __launch_bounds__(256) void k3_softmax()
{
    const int warp = threadIdx.x >> 5, lane = threadIdx.x & 31;
    const size_t row = (size_t)blockIdx.x * 8 + warp;
    const float mx = dec_f(g_rowmax[row]);
    float4* S4 = (float4*)(g_S + row * NN);

    float s = 0.f;
#pragma unroll 4
    for (int it = lane; it < NN / 4; it += 32) {
        float4 v = S4[it];
        v.x = fast_exp(v.x - mx);
        v.y = fast_exp(v.y - mx);
        v.z = fast_exp(v.z - mx);
        v.w = fast_exp(v.w - mx);
        s += (v.x + v.y) + (v.z + v.w);
        v.x = tf32r(v.x); v.y = tf32r(v.y); v.z = tf32r(v.z); v.w = tf32r(v.w);
        S4[it] = v;
    }
#pragma unroll
    for (int o = 16; o; o >>= 1) s += __shfl_xor_sync(0xffffffffu, s, o);
    const float z = 1.0f / s;

    float4* gv4 = (float4*)(g_gv + row * CHH);
    float4 v = gv4[lane];
    v.x = tf32r(v.x * z); v.y = tf32r(v.y * z);
    v.z = tf32r(v.z * z); v.w = tf32r(v.w * z);
    gv4[lane] = v;
}

// ================= K4: O[i][c] = sum_j P[j][i]*g'[j][c]  (TF32, 4-stage, no-cvt) ====
#define K4_PA 68
#define K4_PB 132
__global__ __launch_bounds__(256) void k4_av_mma()
{
    __shared__ float As[4][BK * K4_PA];   // [k(j)][i]   (values pre-rounded to tf32)
    __shared__ float Bs[4][BK * K4_PB];   // [k(j)][c]
    const int b  = blockIdx.y;
    const int i0 = blockIdx.x * 64;
    const int tid = threadIdx.x;
    const int warp = tid >> 5, lane = tid & 31;
    const int g = lane >> 2, t = lane & 3;
    const int wm = (warp >> 2) * 32;
    const int wn = (warp & 3) * 32;
    const float* Sb = g_S  + (size_t)b * NN * NN;
    const float* gv = g_gv + (size_t)b * NN * CHH;

    const int ar = tid >> 4, ac = (tid & 15) * 4;
    const int b0r = tid >> 5,         b0c = (tid & 31) * 4;
    const int b1r = (tid + 256) >> 5, b1c = b0c;

    float acc[2][4][4] = {};

#define K4_LOAD(st, j0)                                                            \
    {                                                                              \
        cp16(&As[st][ar * K4_PA + ac],   Sb + (size_t)((j0) + ar) * NN + i0 + ac); \
        cp16(&Bs[st][b0r * K4_PB + b0c], gv + (size_t)((j0) + b0r) * CHH + b0c);   \
        cp16(&Bs[st][b1r * K4_PB + b1c], gv + (size_t)((j0) + b1r) * CHH + b1c);   \
    }

    K4_LOAD(0, 0);
    asm volatile("cp.async.commit_group;");
    K4_LOAD(1, BK);
    asm volatile("cp.async.commit_group;");
    K4_LOAD(2, 2 * BK);
    asm volatile("cp.async.commit_group;");

#pragma unroll 1
    for (int it = 0; it < NN / BK; ++it) {
        const int s = it & 3;
        asm volatile("cp.async.wait_group 2;");
        __syncthreads();   // all warps done with stage (it-1); stage s is resident

        if (it + 3 < NN / BK) K4_LOAD((it + 3) & 3, (it + 3) * BK);
        asm volatile("cp.async.commit_group;");

#pragma unroll
        for (int ks = 0; ks < BK; ks += 8) {
            unsigned af[2][4], bf[4][2];
#pragma unroll
            for (int mi = 0; mi < 2; ++mi) {
                int m = wm + mi * 16 + g;
                af[mi][0] = *(const unsigned*)&As[s][(ks + t)     * K4_PA + m];
                af[mi][1] = *(const unsigned*)&As[s][(ks + t)     * K4_PA + m + 8];
                af[mi][2] = *(const unsigned*)&As[s][(ks + t + 4) * K4_PA + m];
                af[mi][3] = *(const unsigned*)&As[s][(ks + t + 4) * K4_PA + m + 8];
            }
#pragma unroll
            for (int ni = 0; ni < 4; ++ni) {
                int n = wn + ni * 8 + g;
                bf[ni][0] = *(const unsigned*)&Bs[s][(ks + t)     * K4_PB + n];
                bf[ni][1] = *(const unsigned*)&Bs[s][(ks + t + 4) * K4_PB + n];
            }
#pragma unroll
            for (int mi = 0; mi < 2; ++mi)
#pragma unroll
                for (int ni = 0; ni < 4; ++ni)
                    mma_tf32(acc[mi][ni], af[mi], bf[ni]);
        }
    }

    float* Ob = g_O + (size_t)b * NN * CHH;
#pragma unroll
    for (int mi = 0; mi < 2; ++mi)
#pragma unroll
        for (int ni = 0; ni < 4; ++ni) {
            int i = i0 + wm + mi * 16 + g;
            int c = wn + ni * 8 + t * 2;
            *(float2*)&Ob[(size_t)i * CHH + c] =
                make_float2(acc[mi][ni][0], acc[mi][ni][1]);
            *(float2*)&Ob[(size_t)(i + 8) * CHH + c] =
                make_float2(acc[mi][ni][2], acc[mi][ni][3]);
        }
}

// ================= K5: final projection + bias + residual =================
__global__ __launch_bounds__(256) void k5_out(
    const float* __restrict__ x,
    const float* __restrict__ Ww, const float* __restrict__ Wb,
    float* __restrict__ out)
{
    __shared__ float As[BK * SPITCH];
    __shared__ float Bs[BK * SPITCH];
    const int b  = blockIdx.z;
    const int o0 = blockIdx.y * TILE;
    const int n0 = blockIdx.x * TILE;
    const int tid = threadIdx.x, ty = tid >> 4, tx = tid & 15;
    const float* Ob = g_O + (size_t)b * NN * CHH;

    float acc[8][8] = {};
    for (int k0 = 0; k0 < CHH; k0 += BK) {
#pragma unroll
        for (int it = 0; it < 2; ++it) {
            int idx = tid + it * 256;
            int kk4 = idx & 3, oo = idx >> 2;
            float4 v = *(const float4*)(Ww + (size_t)(o0 + oo) * CHH + k0 + kk4 * 4);
            As[(kk4 * 4 + 0) * SPITCH + oo] = v.x;
            As[(kk4 * 4 + 1) * SPITCH + oo] = v.y;
            As[(kk4 * 4 + 2) * SPITCH + oo] = v.z;
            As[(kk4 * 4 + 3) * SPITCH + oo] = v.w;
        }
#pragma unroll
        for (int it = 0; it < 2; ++it) {
            int idx = tid + it * 256;
            int kk4 = idx & 3, nn = idx >> 2;
            float4 v = *(const float4*)(Ob + (size_t)(n0 + nn) * CHH + k0 + kk4 * 4);
            Bs[(kk4 * 4 + 0) * SPITCH + nn] = v.x;
            Bs[(kk4 * 4 + 1) * SPITCH + nn] = v.y;
            Bs[(kk4 * 4 + 2) * SPITCH + nn] = v.z;
            Bs[(kk4 * 4 + 3) * SPITCH + nn] = v.w;
        }
        __syncthreads();
        gemm_step(As, Bs, acc, ty, tx);
        __syncthreads();
    }

#pragma unroll
    for (int r = 0; r < 8; ++r) {
        int o = o0 + ty * 8 + r;
        float bb = Wb[o];
        const float* xr = x   + (size_t)b * CC * NN + (size_t)o * NN + n0 + tx * 8;
        float*       yr = out + (size_t)b * CC * NN + (size_t)o * NN + n0 + tx * 8;
        float4 x0 = *(const float4*)xr;
        float4 x1 = *(const float4*)(xr + 4);
        *(float4*)yr = make_float4(acc[r][0] + bb + x0.x, acc[r][1] + bb + x0.y,
                                   acc[r][2] + bb + x0.z, acc[r][3] + bb + x0.w);
        *(float4*)(yr + 4) = make_float4(acc[r][4] + bb + x1.x, acc[r][5] + bb + x1.y,
                                         acc[r][6] + bb + x1.z, acc[r][7] + bb + x1.w);
    }
}

// ================= launch =================
extern "C" void kernel_launch(void* const* d_in, const int* in_sizes, int n_in,
                              void* d_out, int out_size) {
    const float* x  = (const float*)d_in[0];
    const float* tw = (const float*)d_in[1];
    const float* tb = (const float*)d_in[2];
    const float* pw = (const float*)d_in[3];
    const float* pb = (const float*)d_in[4];
    const float* gw = (const float*)d_in[5];
    const float* gb = (const float*)d_in[6];
    const float* Ww = (const float*)d_in[7];
    const float* Wb = (const float*)d_in[8];
    float* out = (float*)d_out;

    k0_init      <<<dim3(BB * NN / 256),            256>>>();
    k1_proj      <<<dim3(NN / TILE, 3, BB),         256>>>(x, tw, tb, pw, pb, gw, gb);
    k2_scores_mma<<<dim3(NN / 128, NN / 128, BB),   256>>>();
    k3_softmax   <<<dim3(BB * NN / 8),              256>>>();
    k4_av_mma    <<<dim3(NN / 64, BB),              256>>>();
    k5_out       <<<dim3(NN / TILE, CC / TILE, BB), 256>>>(x, Ww, Wb, out);
}

// round 6
// speedup vs baseline: 2.5661x; 1.2871x over previous
#include <cuda_runtime.h>
#include <cuda_bf16.h>
#include <cuda_fp16.h>

#define BB   4
#define CC   256
#define CHH  128
#define NN   4096

#define TILE   128
#define BK     16
#define SPITCH 132   // 128 + 4 pad

// ---------------- scratch ----------------
__device__ float    g_gv   [(size_t)BB * NN * CHH];   // g fp32 (k1 out, k3 in)
__device__ __half   g_gvh  [(size_t)BB * NN * CHH];   // g/Z fp16 (k3 out, k4 in)
__device__ float    g_O    [(size_t)BB * NN * CHH];   // [b][i][ch]
__device__ float    g_S    [(size_t)BB * NN * NN];    // scores fp32 [b][j][i]
__device__ __half   g_P    [(size_t)BB * NN * NN];    // probs fp16 [b][j][i]
__device__ unsigned g_rowmax[BB * NN];
// split-bf16 theta/phi (big + residual)
__device__ __nv_bfloat16 g_thB[(size_t)BB * NN * CHH];
__device__ __nv_bfloat16 g_thS[(size_t)BB * NN * CHH];
__device__ __nv_bfloat16 g_phB[(size_t)BB * NN * CHH];
__device__ __nv_bfloat16 g_phS[(size_t)BB * NN * CHH];

// ---------------- fast exp (FFMA-only, x <= 0) ----------------
__device__ __forceinline__ float fast_exp(float x) {
    float t = fmaxf(x * 1.4426950408889634f, -120.0f);
    float z = t + 12582912.0f;
    int   e = __float_as_int(z);
    float f = t - (z - 12582912.0f);
    float p = 1.3333558e-3f;
    p = fmaf(p, f, 9.6181291e-3f);
    p = fmaf(p, f, 5.5504109e-2f);
    p = fmaf(p, f, 2.4022651e-1f);
    p = fmaf(p, f, 6.9314718e-1f);
    p = fmaf(p, f, 1.0f);
    return __int_as_float((e << 23) + __float_as_int(p));
}

// ---------------- monotonic float<->uint for atomicMax ----------------
__device__ __forceinline__ unsigned enc_f(float v) {
    unsigned b = __float_as_uint(v);
    return (b & 0x80000000u) ? ~b : (b | 0x80000000u);
}
__device__ __forceinline__ float dec_f(unsigned u) {
    return (u & 0x80000000u) ? __uint_as_float(u & 0x7fffffffu)
                             : __uint_as_float(~u);
}

// ---------------- tensor-core helpers ----------------
__device__ __forceinline__ void mma_bf16(float* d, const unsigned* a, const unsigned* b) {
    asm volatile("mma.sync.aligned.m16n8k16.row.col.f32.bf16.bf16.f32 "
                 "{%0,%1,%2,%3}, {%4,%5,%6,%7}, {%8,%9}, {%0,%1,%2,%3};"
                 : "+f"(d[0]), "+f"(d[1]), "+f"(d[2]), "+f"(d[3])
                 : "r"(a[0]), "r"(a[1]), "r"(a[2]), "r"(a[3]),
                   "r"(b[0]), "r"(b[1]));
}
__device__ __forceinline__ void mma_fp16(float* d, const unsigned* a, const unsigned* b) {
    asm volatile("mma.sync.aligned.m16n8k16.row.col.f32.f16.f16.f32 "
                 "{%0,%1,%2,%3}, {%4,%5,%6,%7}, {%8,%9}, {%0,%1,%2,%3};"
                 : "+f"(d[0]), "+f"(d[1]), "+f"(d[2]), "+f"(d[3])
                 : "r"(a[0]), "r"(a[1]), "r"(a[2]), "r"(a[3]),
                   "r"(b[0]), "r"(b[1]));
}
__device__ __forceinline__ void ldsm4t(unsigned* r, const void* smem) {
    unsigned a = (unsigned)__cvta_generic_to_shared(smem);
    asm volatile("ldmatrix.sync.aligned.m8n8.x4.trans.shared.b16 {%0,%1,%2,%3}, [%4];"
                 : "=r"(r[0]), "=r"(r[1]), "=r"(r[2]), "=r"(r[3]) : "r"(a));
}
__device__ __forceinline__ void cp16(void* smem, const void* g) {
    unsigned a = (unsigned)__cvta_generic_to_shared(smem);
    asm volatile("cp.async.cg.shared.global [%0], [%1], 16;" :: "r"(a), "l"(g));
}
// split a float2 into packed bf16x2 (big) + packed bf16x2 (residual)
__device__ __forceinline__ void split2(float v0, float v1, unsigned& big, unsigned& sml) {
    asm("cvt.rn.bf16x2.f32 %0, %1, %2;" : "=r"(big) : "f"(v1), "f"(v0));
    float b0 = __uint_as_float(big << 16);
    float b1 = __uint_as_float(big & 0xffff0000u);
    float r0 = v0 - b0, r1 = v1 - b1;
    asm("cvt.rn.bf16x2.f32 %0, %1, %2;" : "=r"(sml) : "f"(r1), "f"(r0));
}

// ---------------- SIMT 8x8 micro GEMM (k1/k5) ----------------
__device__ __forceinline__ void gemm_step(const float* __restrict__ As,
                                          const float* __restrict__ Bs,
                                          float (&acc)[8][8], int ty, int tx) {
#pragma unroll
    for (int k = 0; k < BK; ++k) {
        float a[8], b[8];
        *(float4*)&a[0] = *(const float4*)&As[k * SPITCH + ty * 8];
        *(float4*)&a[4] = *(const float4*)&As[k * SPITCH + ty * 8 + 4];
        *(float4*)&b[0] = *(const float4*)&Bs[k * SPITCH + tx * 8];
        *(float4*)&b[4] = *(const float4*)&Bs[k * SPITCH + tx * 8 + 4];
#pragma unroll
        for (int r = 0; r < 8; ++r)
#pragma unroll
            for (int c = 0; c < 8; ++c)
                acc[r][c] = fmaf(a[r], b[c], acc[r][c]);
    }
}

// ================= K0: init rowmax =================
__global__ __launch_bounds__(256) void k0_init() {
    g_rowmax[blockIdx.x * 256 + threadIdx.x] = 0u;
}

// ================= K1: theta/phi/g projections =================
__global__ __launch_bounds__(256) void k1_proj(
    const float* __restrict__ x,
    const float* __restrict__ tw, const float* __restrict__ tb,
    const float* __restrict__ pw, const float* __restrict__ pb,
    const float* __restrict__ gw, const float* __restrict__ gb)
{
    __shared__ float As[BK * SPITCH];
    __shared__ float Bs[BK * SPITCH];
    const int b    = blockIdx.z;
    const int proj = blockIdx.y;
    const int n0   = blockIdx.x * TILE;
    const float* w    = proj == 0 ? tw : (proj == 1 ? pw : gw);
    const float* bias = proj == 0 ? tb : (proj == 1 ? pb : gb);

    const int tid = threadIdx.x, ty = tid >> 4, tx = tid & 15;
    const float* xb = x + (size_t)b * CC * NN;

    float acc[8][8] = {};
    for (int k0 = 0; k0 < CC; k0 += BK) {
#pragma unroll
        for (int it = 0; it < 2; ++it) {
            int idx = tid + it * 256;
            int nn4 = idx & 31, kk = idx >> 5;
            *(float4*)&As[kk * SPITCH + nn4 * 4] =
                *(const float4*)(xb + (size_t)(k0 + kk) * NN + n0 + nn4 * 4);
        }
#pragma unroll
        for (int it = 0; it < 2; ++it) {
            int idx = tid + it * 256;
            int kk4 = idx & 3, o = idx >> 2;
            float4 v = *(const float4*)(w + (size_t)o * CC + k0 + kk4 * 4);
            Bs[(kk4 * 4 + 0) * SPITCH + o] = v.x;
            Bs[(kk4 * 4 + 1) * SPITCH + o] = v.y;
            Bs[(kk4 * 4 + 2) * SPITCH + o] = v.z;
            Bs[(kk4 * 4 + 3) * SPITCH + o] = v.w;
        }
        __syncthreads();
        gemm_step(As, Bs, acc, ty, tx);
        __syncthreads();
    }

    float bi[8];
#pragma unroll
    for (int c = 0; c < 8; ++c) bi[c] = bias[tx * 8 + c];

    if (proj < 2) {
        __nv_bfloat16* outB = proj == 0 ? g_thB : g_phB;
        __nv_bfloat16* outS = proj == 0 ? g_thS : g_phS;
        size_t base = (size_t)b * NN * CHH;
#pragma unroll
        for (int r = 0; r < 8; ++r) {
            int n = n0 + ty * 8 + r;
            unsigned pb4[4], ps4[4];
#pragma unroll
            for (int c = 0; c < 4; ++c)
                split2(acc[r][2 * c] + bi[2 * c], acc[r][2 * c + 1] + bi[2 * c + 1],
                       pb4[c], ps4[c]);
            *(uint4*)&outB[base + (size_t)n * CHH + tx * 8] =
                make_uint4(pb4[0], pb4[1], pb4[2], pb4[3]);
            *(uint4*)&outS[base + (size_t)n * CHH + tx * 8] =
                make_uint4(ps4[0], ps4[1], ps4[2], ps4[3]);
        }
    } else {
        float* ob = g_gv + (size_t)b * NN * CHH;
#pragma unroll
        for (int r = 0; r < 8; ++r) {
            int n = n0 + ty * 8 + r;
            *(float4*)&ob[(size_t)n * CHH + tx * 8] =
                make_float4(acc[r][0] + bi[0], acc[r][1] + bi[1],
                            acc[r][2] + bi[2], acc[r][3] + bi[3]);
            *(float4*)&ob[(size_t)n * CHH + tx * 8 + 4] =
                make_float4(acc[r][4] + bi[4], acc[r][5] + bi[5],
                            acc[r][6] + bi[6], acc[r][7] + bi[7]);
        }
    }
}

// ================= K2: S = theta . phi^T (split-bf16 x3, cp.async, fused rowmax) ===
#define K2P 24
__global__ __launch_bounds__(256) void k2_scores_mma()
{
    __shared__ __align__(16) __nv_bfloat16 sm[2][4][128 * K2P];
    const int b  = blockIdx.z;
    const int j0 = blockIdx.y * 128;
    const int i0 = blockIdx.x * 128;
    const int tid = threadIdx.x;
    const int warp = tid >> 5, lane = tid & 31;
    const int g = lane >> 2, t = lane & 3;
    const int wm = (warp >> 2) * 64;
    const int wn = (warp & 3) * 32;
    const size_t baseJ = (size_t)b * NN * CHH + (size_t)j0 * CHH;
    const size_t baseI = (size_t)b * NN * CHH + (size_t)i0 * CHH;
    const __nv_bfloat16* thB = g_thB + baseJ;
    const __nv_bfloat16* thS = g_thS + baseJ;
    const __nv_bfloat16* phB = g_phB + baseI;
    const __nv_bfloat16* phS = g_phS + baseI;

    float acc[4][4][4] = {};

    const int lrow = tid >> 1, lkc = (tid & 1) * 8;
#define K2_LOAD(st, k0)                                                        \
    {                                                                          \
        cp16(&sm[st][0][lrow * K2P + lkc], thB + (size_t)lrow * CHH + (k0) + lkc); \
        cp16(&sm[st][1][lrow * K2P + lkc], thS + (size_t)lrow * CHH + (k0) + lkc); \
        cp16(&sm[st][2][lrow * K2P + lkc], phB + (size_t)lrow * CHH + (k0) + lkc); \
        cp16(&sm[st][3][lrow * K2P + lkc], phS + (size_t)lrow * CHH + (k0) + lkc); \
    }

    K2_LOAD(0, 0);
    asm volatile("cp.async.commit_group;");

#pragma unroll 1
    for (int it = 0; it < CHH / BK; ++it) {
        const int s = it & 1;
        if (it + 1 < CHH / BK) K2_LOAD(s ^ 1, (it + 1) * BK);
        asm volatile("cp.async.commit_group;");
        asm volatile("cp.async.wait_group 1;");
        __syncthreads();

        const __nv_bfloat16* AB = sm[s][0];
        const __nv_bfloat16* AS = sm[s][1];
        const __nv_bfloat16* PB = sm[s][2];
        const __nv_bfloat16* PS = sm[s][3];

        unsigned aB[4][4], aS[4][4], bB[4][2], bS[4][2];
#pragma unroll
        for (int mi = 0; mi < 4; ++mi) {
            int m = wm + mi * 16 + g;
            aB[mi][0] = *(const unsigned*)&AB[m * K2P + 2 * t];
            aB[mi][1] = *(const unsigned*)&AB[(m + 8) * K2P + 2 * t];
            aB[mi][2] = *(const unsigned*)&AB[m * K2P + 2 * t + 8];
            aB[mi][3] = *(const unsigned*)&AB[(m + 8) * K2P + 2 * t + 8];
            aS[mi][0] = *(const unsigned*)&AS[m * K2P + 2 * t];
            aS[mi][1] = *(const unsigned*)&AS[(m + 8) * K2P + 2 * t];
            aS[mi][2] = *(const unsigned*)&AS[m * K2P + 2 * t + 8];
            aS[mi][3] = *(const unsigned*)&AS[(m + 8) * K2P + 2 * t + 8];
        }
#pragma unroll
        for (int ni = 0; ni < 4; ++ni) {
            int n = wn + ni * 8 + g;
            bB[ni][0] = *(const unsigned*)&PB[n * K2P + 2 * t];
            bB[ni][1] = *(const unsigned*)&PB[n * K2P + 2 * t + 8];
            bS[ni][0] = *(const unsigned*)&PS[n * K2P + 2 * t];
            bS[ni][1] = *(const unsigned*)&PS[n * K2P + 2 * t + 8];
        }
#pragma unroll
        for (int mi = 0; mi < 4; ++mi)
#pragma unroll
            for (int ni = 0; ni < 4; ++ni) {
                mma_bf16(acc[mi][ni], aB[mi], bS[ni]);
                mma_bf16(acc[mi][ni], aS[mi], bB[ni]);
                mma_bf16(acc[mi][ni], aB[mi], bB[ni]);
            }
        __syncthreads();
    }

    float* Sb = g_S + (size_t)b * NN * NN;
#pragma unroll
    for (int mi = 0; mi < 4; ++mi) {
        int j = j0 + wm + mi * 16 + g;
        float r0 = -3.0e38f, r1 = -3.0e38f;
#pragma unroll
        for (int ni = 0; ni < 4; ++ni) {
            int i = i0 + wn + ni * 8 + t * 2;
            *(float2*)&Sb[(size_t)j * NN + i] =
                make_float2(acc[mi][ni][0], acc[mi][ni][1]);
            *(float2*)&Sb[(size_t)(j + 8) * NN + i] =
                make_float2(acc[mi][ni][2], acc[mi][ni][3]);
            r0 = fmaxf(r0, fmaxf(acc[mi][ni][0], acc[mi][ni][1]));
            r1 = fmaxf(r1, fmaxf(acc[mi][ni][2], acc[mi][ni][3]));
        }
        r0 = fmaxf(r0, __shfl_xor_sync(0xffffffffu, r0, 1));
        r0 = fmaxf(r0, __shfl_xor_sync(0xffffffffu, r0, 2));
        r1 = fmaxf(r1, __shfl_xor_sync(0xffffffffu, r1, 1));
        r1 = fmaxf(r1, __shfl_xor_sync(0xffffffffu, r1, 2));
        if (t == 0) {
            atomicMax(&g_rowmax[b * NN + j],     enc_f(r0));
            atomicMax(&g_rowmax[b * NN + j + 8], enc_f(r1));
        }
    }
}

// ================= K3: read S fp32, write P fp16; fold 1/Z into g (fp16) =========
__global__ __launch_bounds__(256) void k3_softmax()
{
    const int warp = threadIdx.x >> 5, lane = threadIdx.x & 31;
    const size_t row = (size_t)blockIdx.x * 8 + warp;
    const float mx = dec_f(g_rowmax[row]);
    const float4* S4 = (const float4*)(g_S + row * NN);
    uint2* P2 = (uint2*)(g_P + row * NN);

    float s = 0.f;
#pragma unroll 4
    for (int it = lane; it < NN / 4; it += 32) {
        float4 v = S4[it];
        v.x = fast_exp(v.x - mx);
        v.y = fast_exp(v.y - mx);
        v.z = fast_exp(v.z - mx);
        v.w = fast_exp(v.w - mx);
        s += (v.x + v.y) + (v.z + v.w);
        __half2 h0 = __floats2half2_rn(v.x, v.y);
        __half2 h1 = __floats2half2_rn(v.z, v.w);
        P2[it] = make_uint2(*(unsigned*)&h0, *(unsigned*)&h1);
    }
#pragma unroll
    for (int o = 16; o; o >>= 1) s += __shfl_xor_sync(0xffffffffu, s, o);
    const float z = 1.0f / s;

    const float4* gv4 = (const float4*)(g_gv + row * CHH);
    uint2* gh2 = (uint2*)(g_gvh + row * CHH);
    float4 v = gv4[lane];
    __half2 h0 = __floats2half2_rn(v.x * z, v.y * z);
    __half2 h1 = __floats2half2_rn(v.z * z, v.w * z);
    gh2[lane] = make_uint2(*(unsigned*)&h0, *(unsigned*)&h1);
}

// ================= K4: O[i][c] = sum_j P[j][i]*g'[j][c]  (fp16 mma, ldmatrix) =====
// tile 64(i) x 128(c), BK=32, 3-stage cp.async; 8 warps = 2(m:32) x 4(n:32)
#define K4BK  32
#define K4_PA 72    // fp16 pitch, rows shift 144B -> LDSM conflict-free
#define K4_PB 136   // fp16 pitch, 272B
__global__ __launch_bounds__(256) void k4_av_fp16()
{
    __shared__ __align__(16) __half As[3][K4BK * K4_PA];   // [k(j)][i]
    __shared__ __align__(16) __half Bs[3][K4BK * K4_PB];   // [k(j)][c]
    const int b  = blockIdx.y;
    const int i0 = blockIdx.x * 64;
    const int tid = threadIdx.x;
    const int warp = tid >> 5, lane = tid & 31;
    const int g = lane >> 2, t = lane & 3;
    const int wm = (warp >> 2) * 32;
    const int wn = (warp & 3) * 32;
    const __half* Pb = g_P   + (size_t)b * NN * NN;
    const __half* gh = g_gvh + (size_t)b * NN * CHH;

    // ldmatrix lane address components
    const int krA = (lane & 7) + ((lane & 16) ? 8 : 0);
    const int mcA = (lane & 8) ? 8 : 0;
    const int krB = (lane & 7) + ((lane & 8) ? 8 : 0);
    const int ncB = (lane & 16) ? 8 : 0;

    // loaders
    const int arow = tid >> 3, acol = (tid & 7) * 8;             // As: 1 chunk
    const int brow0 = tid >> 4, bcol = (tid & 15) * 8;           // Bs: 2 chunks
    const int brow1 = brow0 + 16;

    float acc[2][4][4] = {};

#define K4_LOAD(st, j0)                                                          \
    {                                                                            \
        cp16(&As[st][arow * K4_PA + acol],  Pb + (size_t)((j0) + arow) * NN + i0 + acol); \
        cp16(&Bs[st][brow0 * K4_PB + bcol], gh + (size_t)((j0) + brow0) * CHH + bcol);    \
        cp16(&Bs[st][brow1 * K4_PB + bcol], gh + (size_t)((j0) + brow1) * CHH + bcol);    \
    }

    K4_LOAD(0, 0);
    asm volatile("cp.async.commit_group;");
    K4_LOAD(1, K4BK);
    asm volatile("cp.async.commit_group;");

    int s = 0;
#pragma unroll 1
    for (int it = 0; it < NN / K4BK; ++it) {
        asm volatile("cp.async.wait_group 1;");
        __syncthreads();

        if (it + 2 < NN / K4BK) {
            int st = s + 2; if (st >= 3) st -= 3;
            K4_LOAD(st, (it + 2) * K4BK);
        }
        asm volatile("cp.async.commit_group;");

#pragma unroll
        for (int ks = 0; ks < K4BK; ks += 16) {
            unsigned a[2][4], bq[2][4];
#pragma unroll
            for (int mi = 0; mi < 2; ++mi)
                ldsm4t(a[mi], &As[s][(ks + krA) * K4_PA + wm + mi * 16 + mcA]);
#pragma unroll
            for (int nb = 0; nb < 2; ++nb)
                ldsm4t(bq[nb], &Bs[s][(ks + krB) * K4_PB + wn + nb * 16 + ncB]);
#pragma unroll
            for (int mi = 0; mi < 2; ++mi)
#pragma unroll
                for (int ni = 0; ni < 4; ++ni)
                    mma_fp16(acc[mi][ni], a[mi], &bq[ni >> 1][(ni & 1) * 2]);
        }
        __syncthreads();
        if (++s == 3) s = 0;
    }

    float* Ob = g_O + (size_t)b * NN * CHH;
#pragma unroll
    for (int mi = 0; mi < 2; ++mi)
#pragma unroll
        for (int ni = 0; ni < 4; ++ni) {
            int i = i0 + wm + mi * 16 + g;
            int c = wn + ni * 8 + t * 2;
            *(float2*)&Ob[(size_t)i * CHH + c] =
                make_float2(acc[mi][ni][0], acc[mi][ni][1]);
            *(float2*)&Ob[(size_t)(i + 8) * CHH + c] =
                make_float2(acc[mi][ni][2], acc[mi][ni][3]);
        }
}

// ================= K5: final projection + bias + residual =================
__global__ __launch_bounds__(256) void k5_out(
    const float* __restrict__ x,
    const float* __restrict__ Ww, const float* __restrict__ Wb,
    float* __restrict__ out)
{
    __shared__ float As[BK * SPITCH];
    __shared__ float Bs[BK * SPITCH];
    const int b  = blockIdx.z;
    const int o0 = blockIdx.y * TILE;
    const int n0 = blockIdx.x * TILE;
    const int tid = threadIdx.x, ty = tid >> 4, tx = tid & 15;
    const float* Ob = g_O + (size_t)b * NN * CHH;

    float acc[8][8] = {};
    for (int k0 = 0; k0 < CHH; k0 += BK) {
#pragma unroll
        for (int it = 0; it < 2; ++it) {
            int idx = tid + it * 256;
            int kk4 = idx & 3, oo = idx >> 2;
            float4 v = *(const float4*)(Ww + (size_t)(o0 + oo) * CHH + k0 + kk4 * 4);
            As[(kk4 * 4 + 0) * SPITCH + oo] = v.x;
            As[(kk4 * 4 + 1) * SPITCH + oo] = v.y;
            As[(kk4 * 4 + 2) * SPITCH + oo] = v.z;
            As[(kk4 * 4 + 3) * SPITCH + oo] = v.w;
        }
#pragma unroll
        for (int it = 0; it < 2; ++it) {
            int idx = tid + it * 256;
            int kk4 = idx & 3, nn = idx >> 2;
            float4 v = *(const float4*)(Ob + (size_t)(n0 + nn) * CHH + k0 + kk4 * 4);
            Bs[(kk4 * 4 + 0) * SPITCH + nn] = v.x;
            Bs[(kk4 * 4 + 1) * SPITCH + nn] = v.y;
            Bs[(kk4 * 4 + 2) * SPITCH + nn] = v.z;
            Bs[(kk4 * 4 + 3) * SPITCH + nn] = v.w;
        }
        __syncthreads();
        gemm_step(As, Bs, acc, ty, tx);
        __syncthreads();
    }

#pragma unroll
    for (int r = 0; r < 8; ++r) {
        int o = o0 + ty * 8 + r;
        float bb = Wb[o];
        const float* xr = x   + (size_t)b * CC * NN + (size_t)o * NN + n0 + tx * 8;
        float*       yr = out + (size_t)b * CC * NN + (size_t)o * NN + n0 + tx * 8;
        float4 x0 = *(const float4*)xr;
        float4 x1 = *(const float4*)(xr + 4);
        *(float4*)yr = make_float4(acc[r][0] + bb + x0.x, acc[r][1] + bb + x0.y,
                                   acc[r][2] + bb + x0.z, acc[r][3] + bb + x0.w);
        *(float4*)(yr + 4) = make_float4(acc[r][4] + bb + x1.x, acc[r][5] + bb + x1.y,
                                         acc[r][6] + bb + x1.z, acc[r][7] + bb + x1.w);
    }
}

// ================= launch =================
extern "C" void kernel_launch(void* const* d_in, const int* in_sizes, int n_in,
                              void* d_out, int out_size) {
    const float* x  = (const float*)d_in[0];
    const float* tw = (const float*)d_in[1];
    const float* tb = (const float*)d_in[2];
    const float* pw = (const float*)d_in[3];
    const float* pb = (const float*)d_in[4];
    const float* gw = (const float*)d_in[5];
    const float* gb = (const float*)d_in[6];
    const float* Ww = (const float*)d_in[7];
    const float* Wb = (const float*)d_in[8];
    float* out = (float*)d_out;

    k0_init      <<<dim3(BB * NN / 256),            256>>>();
    k1_proj      <<<dim3(NN / TILE, 3, BB),         256>>>(x, tw, tb, pw, pb, gw, gb);
    k2_scores_mma<<<dim3(NN / 128, NN / 128, BB),   256>>>();
    k3_softmax   <<<dim3(BB * NN / 8),              256>>>();
    k4_av_fp16   <<<dim3(NN / 64, BB),              256>>>();
    k5_out       <<<dim3(NN / TILE, CC / TILE, BB), 256>>>(x, Ww, Wb, out);
}

// round 7
// speedup vs baseline: 2.8870x; 1.1250x over previous
#include <cuda_runtime.h>
#include <cuda_bf16.h>
#include <cuda_fp16.h>

#define BB   4
#define CC   256
#define CHH  128
#define NN   4096

#define TILE   128
#define BK     16
#define SPITCH 132   // 128 + 4 pad

// ---------------- scratch ----------------
__device__ float    g_gv   [(size_t)BB * NN * CHH];   // g fp32 (k1 out, k3 in)
__device__ __half   g_gvh  [(size_t)BB * NN * CHH];   // g/Z fp16 (k3 out, k4 in)
__device__ float    g_O    [(size_t)BB * NN * CHH];   // [b][i][ch]
__device__ float    g_S    [(size_t)BB * NN * NN];    // scores fp32 [b][j][i]
__device__ __half   g_P    [(size_t)BB * NN * NN];    // probs fp16 [b][j][i]
__device__ unsigned g_rowmax[BB * NN];
// split-bf16 theta/phi (big + residual)
__device__ __nv_bfloat16 g_thB[(size_t)BB * NN * CHH];
__device__ __nv_bfloat16 g_thS[(size_t)BB * NN * CHH];
__device__ __nv_bfloat16 g_phB[(size_t)BB * NN * CHH];
__device__ __nv_bfloat16 g_phS[(size_t)BB * NN * CHH];
// split-bf16 x (A operand for k1) and transposed weights (B operand for k1)
__device__ __nv_bfloat16 g_xB [(size_t)BB * CC * NN];
__device__ __nv_bfloat16 g_xS [(size_t)BB * CC * NN];
__device__ __nv_bfloat16 g_wTB[3 * CC * CHH];          // [proj][c][o]
__device__ __nv_bfloat16 g_wTS[3 * CC * CHH];

// ---------------- fast exp (FFMA-only, x <= 0) ----------------
__device__ __forceinline__ float fast_exp(float x) {
    float t = fmaxf(x * 1.4426950408889634f, -120.0f);
    float z = t + 12582912.0f;
    int   e = __float_as_int(z);
    float f = t - (z - 12582912.0f);
    float p = 1.3333558e-3f;
    p = fmaf(p, f, 9.6181291e-3f);
    p = fmaf(p, f, 5.5504109e-2f);
    p = fmaf(p, f, 2.4022651e-1f);
    p = fmaf(p, f, 6.9314718e-1f);
    p = fmaf(p, f, 1.0f);
    return __int_as_float((e << 23) + __float_as_int(p));
}

// ---------------- monotonic float<->uint for atomicMax ----------------
__device__ __forceinline__ unsigned enc_f(float v) {
    unsigned b = __float_as_uint(v);
    return (b & 0x80000000u) ? ~b : (b | 0x80000000u);
}
__device__ __forceinline__ float dec_f(unsigned u) {
    return (u & 0x80000000u) ? __uint_as_float(u & 0x7fffffffu)
                             : __uint_as_float(~u);
}

// ---------------- tensor-core helpers ----------------
__device__ __forceinline__ void mma_bf16(float* d, const unsigned* a, const unsigned* b) {
    asm volatile("mma.sync.aligned.m16n8k16.row.col.f32.bf16.bf16.f32 "
                 "{%0,%1,%2,%3}, {%4,%5,%6,%7}, {%8,%9}, {%0,%1,%2,%3};"
                 : "+f"(d[0]), "+f"(d[1]), "+f"(d[2]), "+f"(d[3])
                 : "r"(a[0]), "r"(a[1]), "r"(a[2]), "r"(a[3]),
                   "r"(b[0]), "r"(b[1]));
}
__device__ __forceinline__ void mma_fp16(float* d, const unsigned* a, const unsigned* b) {
    asm volatile("mma.sync.aligned.m16n8k16.row.col.f32.f16.f16.f32 "
                 "{%0,%1,%2,%3}, {%4,%5,%6,%7}, {%8,%9}, {%0,%1,%2,%3};"
                 : "+f"(d[0]), "+f"(d[1]), "+f"(d[2]), "+f"(d[3])
                 : "r"(a[0]), "r"(a[1]), "r"(a[2]), "r"(a[3]),
                   "r"(b[0]), "r"(b[1]));
}
__device__ __forceinline__ void ldsm4t(unsigned* r, const void* smem) {
    unsigned a = (unsigned)__cvta_generic_to_shared(smem);
    asm volatile("ldmatrix.sync.aligned.m8n8.x4.trans.shared.b16 {%0,%1,%2,%3}, [%4];"
                 : "=r"(r[0]), "=r"(r[1]), "=r"(r[2]), "=r"(r[3]) : "r"(a));
}
__device__ __forceinline__ void ldsm4(unsigned* r, const void* smem) {
    unsigned a = (unsigned)__cvta_generic_to_shared(smem);
    asm volatile("ldmatrix.sync.aligned.m8n8.x4.shared.b16 {%0,%1,%2,%3}, [%4];"
                 : "=r"(r[0]), "=r"(r[1]), "=r"(r[2]), "=r"(r[3]) : "r"(a));
}
__device__ __forceinline__ void cp16(void* smem, const void* g) {
    unsigned a = (unsigned)__cvta_generic_to_shared(smem);
    asm volatile("cp.async.cg.shared.global [%0], [%1], 16;" :: "r"(a), "l"(g));
}
// split a float2 into packed bf16x2 (big) + packed bf16x2 (residual)
__device__ __forceinline__ void split2(float v0, float v1, unsigned& big, unsigned& sml) {
    asm("cvt.rn.bf16x2.f32 %0, %1, %2;" : "=r"(big) : "f"(v1), "f"(v0));
    float b0 = __uint_as_float(big << 16);
    float b1 = __uint_as_float(big & 0xffff0000u);
    float r0 = v0 - b0, r1 = v1 - b1;
    asm("cvt.rn.bf16x2.f32 %0, %1, %2;" : "=r"(sml) : "f"(r1), "f"(r0));
}

// ================= K0: init rowmax =================
__global__ __launch_bounds__(256) void k0_init() {
    g_rowmax[blockIdx.x * 256 + threadIdx.x] = 0u;
}

// ================= K0x: split x -> bf16 big/small planes =================
__global__ __launch_bounds__(256) void k0x_split(const float* __restrict__ x) {
    size_t i4 = (size_t)blockIdx.x * 256 + threadIdx.x;   // float4 index
    float4 v = ((const float4*)x)[i4];
    unsigned b0, s0, b1, s1;
    split2(v.x, v.y, b0, s0);
    split2(v.z, v.w, b1, s1);
    ((uint2*)g_xB)[i4] = make_uint2(b0, b1);
    ((uint2*)g_xS)[i4] = make_uint2(s0, s1);
}

// ================= K0w: transpose + split weights -> [proj][c][o] =================
__global__ __launch_bounds__(256) void k0w_split(
    const float* __restrict__ tw, const float* __restrict__ pw,
    const float* __restrict__ gw) {
    int idx = blockIdx.x * 256 + threadIdx.x;   // 3*256*128
    int o = idx & 127;
    int c = (idx >> 7) & 255;
    int p = idx >> 15;
    const float* w = p == 0 ? tw : (p == 1 ? pw : gw);
    float v = w[o * CC + c];
    __nv_bfloat16 big = __float2bfloat16(v);
    __nv_bfloat16 sml = __float2bfloat16(v - __bfloat162float(big));
    g_wTB[idx] = big;
    g_wTS[idx] = sml;
}

// ================= K1: projections via split-bf16 x3 mma =================
// tile 64(n) x 128(o), k=c 256, BK=16, 3-stage; 8 warps = 2(m:32) x 4(n:32)
#define K1_PA 72     // As pitch (bf16): rows 144 B apart
#define K1_PB 136    // Bs pitch: 272 B
__global__ __launch_bounds__(256) void k1_mma(
    const float* __restrict__ tb, const float* __restrict__ pb,
    const float* __restrict__ gb)
{
    __shared__ __align__(16) __nv_bfloat16 As[3][2][BK * K1_PA];  // [k(c)][n]
    __shared__ __align__(16) __nv_bfloat16 Bs[3][2][BK * K1_PB];  // [k(c)][o]
    const int b    = blockIdx.z;
    const int proj = blockIdx.y;
    const int i0   = blockIdx.x * 64;
    const int tid  = threadIdx.x;
    const int warp = tid >> 5, lane = tid & 31;
    const int g = lane >> 2, t = lane & 3;
    const int wm = (warp >> 2) * 32;
    const int wn = (warp & 3) * 32;

    const __nv_bfloat16* xB = g_xB + (size_t)b * CC * NN;
    const __nv_bfloat16* xS = g_xS + (size_t)b * CC * NN;
    const __nv_bfloat16* wB = g_wTB + (size_t)proj * CC * CHH;
    const __nv_bfloat16* wS = g_wTS + (size_t)proj * CC * CHH;
    const float* bias = proj == 0 ? tb : (proj == 1 ? pb : gb);

    // trans-LDSM lane address components (k4-proven mapping)
    const int krA = (lane & 7) + ((lane & 16) ? 8 : 0);
    const int mcA = (lane & 8) ? 8 : 0;
    const int krB = (lane & 7) + ((lane & 8) ? 8 : 0);
    const int ncB = (lane & 16) ? 8 : 0;

    // loaders: As 2var x 128 chunks (1/thread); Bs 2var x 256 chunks (2/thread)
    const int av  = tid >> 7, ac = tid & 127;
    const int ar  = ac >> 3, acol = (ac & 7) * 8;
    float acc[2][4][4] = {};

#define K1_LOAD(st, k0)                                                              \
    {                                                                                \
        const __nv_bfloat16* xa = av ? xS : xB;                                      \
        cp16(&As[st][av][ar * K1_PA + acol],                                         \
             xa + (size_t)((k0) + ar) * NN + i0 + acol);                             \
        _Pragma("unroll")                                                            \
        for (int q = 0; q < 2; ++q) {                                                \
            int idx = tid + q * 256;                                                 \
            int bv = idx >> 8, cc = idx & 255;                                       \
            int br = cc >> 4, bcol = (cc & 15) * 8;                                  \
            const __nv_bfloat16* wa = bv ? wS : wB;                                  \
            cp16(&Bs[st][bv][br * K1_PB + bcol],                                     \
                 wa + (size_t)((k0) + br) * CHH + bcol);                             \
        }                                                                            \
    }

    K1_LOAD(0, 0);
    asm volatile("cp.async.commit_group;");
    K1_LOAD(1, BK);
    asm volatile("cp.async.commit_group;");

    int s = 0;
#pragma unroll 1
    for (int it = 0; it < CC / BK; ++it) {
        asm volatile("cp.async.wait_group 1;");
        __syncthreads();

        if (it + 2 < CC / BK) {
            int st = s + 2; if (st >= 3) st -= 3;
            K1_LOAD(st, (it + 2) * BK);
        }
        asm volatile("cp.async.commit_group;");

        unsigned aB[2][4], aS[2][4], bB[2][4], bS[2][4];
#pragma unroll
        for (int mi = 0; mi < 2; ++mi) {
            ldsm4t(aB[mi], &As[s][0][krA * K1_PA + wm + mi * 16 + mcA]);
            ldsm4t(aS[mi], &As[s][1][krA * K1_PA + wm + mi * 16 + mcA]);
        }
#pragma unroll
        for (int nb = 0; nb < 2; ++nb) {
            ldsm4t(bB[nb], &Bs[s][0][krB * K1_PB + wn + nb * 16 + ncB]);
            ldsm4t(bS[nb], &Bs[s][1][krB * K1_PB + wn + nb * 16 + ncB]);
        }
#pragma unroll
        for (int mi = 0; mi < 2; ++mi)
#pragma unroll
            for (int ni = 0; ni < 4; ++ni) {
                mma_bf16(acc[mi][ni], aB[mi], &bS[ni >> 1][(ni & 1) * 2]);
                mma_bf16(acc[mi][ni], aS[mi], &bB[ni >> 1][(ni & 1) * 2]);
                mma_bf16(acc[mi][ni], aB[mi], &bB[ni >> 1][(ni & 1) * 2]);
            }
        __syncthreads();
        if (++s == 3) s = 0;
    }

    if (proj < 2) {
        __nv_bfloat16* outB = proj == 0 ? g_thB : g_phB;
        __nv_bfloat16* outS = proj == 0 ? g_thS : g_phS;
        size_t base = (size_t)b * NN * CHH;
#pragma unroll
        for (int mi = 0; mi < 2; ++mi) {
            int i = i0 + wm + mi * 16 + g;
#pragma unroll
            for (int ni = 0; ni < 4; ++ni) {
                int o = wn + ni * 8 + t * 2;
                float b0 = bias[o], b1 = bias[o + 1];
                unsigned pbv, psv;
                split2(acc[mi][ni][0] + b0, acc[mi][ni][1] + b1, pbv, psv);
                *(unsigned*)&outB[base + (size_t)i * CHH + o] = pbv;
                *(unsigned*)&outS[base + (size_t)i * CHH + o] = psv;
                split2(acc[mi][ni][2] + b0, acc[mi][ni][3] + b1, pbv, psv);
                *(unsigned*)&outB[base + (size_t)(i + 8) * CHH + o] = pbv;
                *(unsigned*)&outS[base + (size_t)(i + 8) * CHH + o] = psv;
            }
        }
    } else {
        float* ob = g_gv + (size_t)b * NN * CHH;
#pragma unroll
        for (int mi = 0; mi < 2; ++mi) {
            int i = i0 + wm + mi * 16 + g;
#pragma unroll
            for (int ni = 0; ni < 4; ++ni) {
                int o = wn + ni * 8 + t * 2;
                float b0 = bias[o], b1 = bias[o + 1];
                *(float2*)&ob[(size_t)i * CHH + o] =
                    make_float2(acc[mi][ni][0] + b0, acc[mi][ni][1] + b1);
                *(float2*)&ob[(size_t)(i + 8) * CHH + o] =
                    make_float2(acc[mi][ni][2] + b0, acc[mi][ni][3] + b1);
            }
        }
    }
}

// ================= K2: S = theta . phi^T (split-bf16 x3, ldmatrix, fused rowmax) ===
#define K2P 24
__global__ __launch_bounds__(256) void k2_scores_mma()
{
    __shared__ __align__(16) __nv_bfloat16 sm[2][4][128 * K2P];
    const int b  = blockIdx.z;
    const int j0 = blockIdx.y * 128;
    const int i0 = blockIdx.x * 128;
    const int tid = threadIdx.x;
    const int warp = tid >> 5, lane = tid & 31;
    const int g = lane >> 2, t = lane & 3;
    const int wm = (warp >> 2) * 64;
    const int wn = (warp & 3) * 32;
    const size_t baseJ = (size_t)b * NN * CHH + (size_t)j0 * CHH;
    const size_t baseI = (size_t)b * NN * CHH + (size_t)i0 * CHH;
    const __nv_bfloat16* thB = g_thB + baseJ;
    const __nv_bfloat16* thS = g_thS + baseJ;
    const __nv_bfloat16* phB = g_phB + baseI;
    const __nv_bfloat16* phS = g_phS + baseI;

    // non-trans LDSM lane addresses
    // A frag order (m0k0, m8k0, m0k8, m8k8):
    const int arow = (lane & 7) + ((lane & 8) ? 8 : 0);
    const int akof = (lane & 16) ? 8 : 0;
    // B frag order (n0k0, n0k8, n8k0, n8k8):
    const int brow = (lane & 7) + ((lane & 16) ? 8 : 0);
    const int bkof = (lane & 8) ? 8 : 0;

    float acc[4][4][4] = {};

    const int lrow = tid >> 1, lkc = (tid & 1) * 8;
#define K2_LOAD(st, k0)                                                        \
    {                                                                          \
        cp16(&sm[st][0][lrow * K2P + lkc], thB + (size_t)lrow * CHH + (k0) + lkc); \
        cp16(&sm[st][1][lrow * K2P + lkc], thS + (size_t)lrow * CHH + (k0) + lkc); \
        cp16(&sm[st][2][lrow * K2P + lkc], phB + (size_t)lrow * CHH + (k0) + lkc); \
        cp16(&sm[st][3][lrow * K2P + lkc], phS + (size_t)lrow * CHH + (k0) + lkc); \
    }

    K2_LOAD(0, 0);
    asm volatile("cp.async.commit_group;");

#pragma unroll 1
    for (int it = 0; it < CHH / BK; ++it) {
        const int s = it & 1;
        if (it + 1 < CHH / BK) K2_LOAD(s ^ 1, (it + 1) * BK);
        asm volatile("cp.async.commit_group;");
        asm volatile("cp.async.wait_group 1;");
        __syncthreads();

        const __nv_bfloat16* AB = sm[s][0];
        const __nv_bfloat16* AS = sm[s][1];
        const __nv_bfloat16* PB = sm[s][2];
        const __nv_bfloat16* PS = sm[s][3];

        unsigned aB[4][4], aS[4][4], bB[2][4], bS[2][4];
#pragma unroll
        for (int mi = 0; mi < 4; ++mi) {
            ldsm4(aB[mi], &AB[(wm + mi * 16 + arow) * K2P + akof]);
            ldsm4(aS[mi], &AS[(wm + mi * 16 + arow) * K2P + akof]);
        }
#pragma unroll
        for (int nb = 0; nb < 2; ++nb) {
            ldsm4(bB[nb], &PB[(wn + nb * 16 + brow) * K2P + bkof]);
            ldsm4(bS[nb], &PS[(wn + nb * 16 + brow) * K2P + bkof]);
        }
#pragma unroll
        for (int mi = 0; mi < 4; ++mi)
#pragma unroll
            for (int ni = 0; ni < 4; ++ni) {
                mma_bf16(acc[mi][ni], aB[mi], &bS[ni >> 1][(ni & 1) * 2]);
                mma_bf16(acc[mi][ni], aS[mi], &bB[ni >> 1][(ni & 1) * 2]);
                mma_bf16(acc[mi][ni], aB[mi], &bB[ni >> 1][(ni & 1) * 2]);
            }
        __syncthreads();
    }

    float* Sb = g_S + (size_t)b * NN * NN;
#pragma unroll
    for (int mi = 0; mi < 4; ++mi) {
        int j = j0 + wm + mi * 16 + g;
        float r0 = -3.0e38f, r1 = -3.0e38f;
#pragma unroll
        for (int ni = 0; ni < 4; ++ni) {
            int i = i0 + wn + ni * 8 + t * 2;
            *(float2*)&Sb[(size_t)j * NN + i] =
                make_float2(acc[mi][ni][0], acc[mi][ni][1]);
            *(float2*)&Sb[(size_t)(j + 8) * NN + i] =
                make_float2(acc[mi][ni][2], acc[mi][ni][3]);
            r0 = fmaxf(r0, fmaxf(acc[mi][ni][0], acc[mi][ni][1]));
            r1 = fmaxf(r1, fmaxf(acc[mi][ni][2], acc[mi][ni][3]));
        }
        r0 = fmaxf(r0, __shfl_xor_sync(0xffffffffu, r0, 1));
        r0 = fmaxf(r0, __shfl_xor_sync(0xffffffffu, r0, 2));
        r1 = fmaxf(r1, __shfl_xor_sync(0xffffffffu, r1, 1));
        r1 = fmaxf(r1, __shfl_xor_sync(0xffffffffu, r1, 2));
        if (t == 0) {
            atomicMax(&g_rowmax[b * NN + j],     enc_f(r0));
            atomicMax(&g_rowmax[b * NN + j + 8], enc_f(r1));
        }
    }
}

// ================= K3: read S fp32, write P fp16; fold 1/Z into g (fp16) =========
__global__ __launch_bounds__(256) void k3_softmax()
{
    const int warp = threadIdx.x >> 5, lane = threadIdx.x & 31;
    const size_t row = (size_t)blockIdx.x * 8 + warp;
    const float mx = dec_f(g_rowmax[row]);
    const float4* S4 = (const float4*)(g_S + row * NN);
    uint2* P2 = (uint2*)(g_P + row * NN);

    float s = 0.f;
#pragma unroll 4
    for (int it = lane; it < NN / 4; it += 32) {
        float4 v = S4[it];
        v.x = fast_exp(v.x - mx);
        v.y = fast_exp(v.y - mx);
        v.z = fast_exp(v.z - mx);
        v.w = fast_exp(v.w - mx);
        s += (v.x + v.y) + (v.z + v.w);
        __half2 h0 = __floats2half2_rn(v.x, v.y);
        __half2 h1 = __floats2half2_rn(v.z, v.w);
        P2[it] = make_uint2(*(unsigned*)&h0, *(unsigned*)&h1);
    }
#pragma unroll
    for (int o = 16; o; o >>= 1) s += __shfl_xor_sync(0xffffffffu, s, o);
    const float z = 1.0f / s;

    const float4* gv4 = (const float4*)(g_gv + row * CHH);
    uint2* gh2 = (uint2*)(g_gvh + row * CHH);
    float4 v = gv4[lane];
    __half2 h0 = __floats2half2_rn(v.x * z, v.y * z);
    __half2 h1 = __floats2half2_rn(v.z * z, v.w * z);
    gh2[lane] = make_uint2(*(unsigned*)&h0, *(unsigned*)&h1);
}

// ================= K4: O[i][c] = sum_j P[j][i]*g'[j][c]  (fp16 mma, ldmatrix) =====
#define K4BK  32
#define K4_PA 72
#define K4_PB 136
__global__ __launch_bounds__(256) void k4_av_fp16()
{
    __shared__ __align__(16) __half As[3][K4BK * K4_PA];
    __shared__ __align__(16) __half Bs[3][K4BK * K4_PB];
    const int b  = blockIdx.y;
    const int i0 = blockIdx.x * 64;
    const int tid = threadIdx.x;
    const int warp = tid >> 5, lane = tid & 31;
    const int g = lane >> 2, t = lane & 3;
    const int wm = (warp >> 2) * 32;
    const int wn = (warp & 3) * 32;
    const __half* Pb = g_P   + (size_t)b * NN * NN;
    const __half* gh = g_gvh + (size_t)b * NN * CHH;

    const int krA = (lane & 7) + ((lane & 16) ? 8 : 0);
    const int mcA = (lane & 8) ? 8 : 0;
    const int krB = (lane & 7) + ((lane & 8) ? 8 : 0);
    const int ncB = (lane & 16) ? 8 : 0;

    const int arow = tid >> 3, acol = (tid & 7) * 8;
    const int brow0 = tid >> 4, bcol = (tid & 15) * 8;
    const int brow1 = brow0 + 16;

    float acc[2][4][4] = {};

#define K4_LOAD(st, j0)                                                          \
    {                                                                            \
        cp16(&As[st][arow * K4_PA + acol],  Pb + (size_t)((j0) + arow) * NN + i0 + acol); \
        cp16(&Bs[st][brow0 * K4_PB + bcol], gh + (size_t)((j0) + brow0) * CHH + bcol);    \
        cp16(&Bs[st][brow1 * K4_PB + bcol], gh + (size_t)((j0) + brow1) * CHH + bcol);    \
    }

    K4_LOAD(0, 0);
    asm volatile("cp.async.commit_group;");
    K4_LOAD(1, K4BK);
    asm volatile("cp.async.commit_group;");

    int s = 0;
#pragma unroll 1
    for (int it = 0; it < NN / K4BK; ++it) {
        asm volatile("cp.async.wait_group 1;");
        __syncthreads();

        if (it + 2 < NN / K4BK) {
            int st = s + 2; if (st >= 3) st -= 3;
            K4_LOAD(st, (it + 2) * K4BK);
        }
        asm volatile("cp.async.commit_group;");

#pragma unroll
        for (int ks = 0; ks < K4BK; ks += 16) {
            unsigned a[2][4], bq[2][4];
#pragma unroll
            for (int mi = 0; mi < 2; ++mi)
                ldsm4t(a[mi], &As[s][(ks + krA) * K4_PA + wm + mi * 16 + mcA]);
#pragma unroll
            for (int nb = 0; nb < 2; ++nb)
                ldsm4t(bq[nb], &Bs[s][(ks + krB) * K4_PB + wn + nb * 16 + ncB]);
#pragma unroll
            for (int mi = 0; mi < 2; ++mi)
#pragma unroll
                for (int ni = 0; ni < 4; ++ni)
                    mma_fp16(acc[mi][ni], a[mi], &bq[ni >> 1][(ni & 1) * 2]);
        }
        __syncthreads();
        if (++s == 3) s = 0;
    }

    float* Ob = g_O + (size_t)b * NN * CHH;
#pragma unroll
    for (int mi = 0; mi < 2; ++mi)
#pragma unroll
        for (int ni = 0; ni < 4; ++ni) {
            int i = i0 + wm + mi * 16 + g;
            int c = wn + ni * 8 + t * 2;
            *(float2*)&Ob[(size_t)i * CHH + c] =
                make_float2(acc[mi][ni][0], acc[mi][ni][1]);
            *(float2*)&Ob[(size_t)(i + 8) * CHH + c] =
                make_float2(acc[mi][ni][2], acc[mi][ni][3]);
        }
}

// ================= K5: final projection + bias + residual (SIMT) =================
__device__ __forceinline__ void gemm_step(const float* __restrict__ As,
                                          const float* __restrict__ Bs,
                                          float (&acc)[8][8], int ty, int tx) {
#pragma unroll
    for (int k = 0; k < BK; ++k) {
        float a[8], b[8];
        *(float4*)&a[0] = *(const float4*)&As[k * SPITCH + ty * 8];
        *(float4*)&a[4] = *(const float4*)&As[k * SPITCH + ty * 8 + 4];
        *(float4*)&b[0] = *(const float4*)&Bs[k * SPITCH + tx * 8];
        *(float4*)&b[4] = *(const float4*)&Bs[k * SPITCH + tx * 8 + 4];
#pragma unroll
        for (int r = 0; r < 8; ++r)
#pragma unroll
            for (int c = 0; c < 8; ++c)
                acc[r][c] = fmaf(a[r], b[c], acc[r][c]);
    }
}

__global__ __launch_bounds__(256) void k5_out(
    const float* __restrict__ x,
    const float* __restrict__ Ww, const float* __restrict__ Wb,
    float* __restrict__ out)
{
    __shared__ float As[BK * SPITCH];
    __shared__ float Bs[BK * SPITCH];
    const int b  = blockIdx.z;
    const int o0 = blockIdx.y * TILE;
    const int n0 = blockIdx.x * TILE;
    const int tid = threadIdx.x, ty = tid >> 4, tx = tid & 15;
    const float* Ob = g_O + (size_t)b * NN * CHH;

    float acc[8][8] = {};
    for (int k0 = 0; k0 < CHH; k0 += BK) {
#pragma unroll
        for (int it = 0; it < 2; ++it) {
            int idx = tid + it * 256;
            int kk4 = idx & 3, oo = idx >> 2;
            float4 v = *(const float4*)(Ww + (size_t)(o0 + oo) * CHH + k0 + kk4 * 4);
            As[(kk4 * 4 + 0) * SPITCH + oo] = v.x;
            As[(kk4 * 4 + 1) * SPITCH + oo] = v.y;
            As[(kk4 * 4 + 2) * SPITCH + oo] = v.z;
            As[(kk4 * 4 + 3) * SPITCH + oo] = v.w;
        }
#pragma unroll
        for (int it = 0; it < 2; ++it) {
            int idx = tid + it * 256;
            int kk4 = idx & 3, nn = idx >> 2;
            float4 v = *(const float4*)(Ob + (size_t)(n0 + nn) * CHH + k0 + kk4 * 4);
            Bs[(kk4 * 4 + 0) * SPITCH + nn] = v.x;
            Bs[(kk4 * 4 + 1) * SPITCH + nn] = v.y;
            Bs[(kk4 * 4 + 2) * SPITCH + nn] = v.z;
            Bs[(kk4 * 4 + 3) * SPITCH + nn] = v.w;
        }
        __syncthreads();
        gemm_step(As, Bs, acc, ty, tx);
        __syncthreads();
    }

#pragma unroll
    for (int r = 0; r < 8; ++r) {
        int o = o0 + ty * 8 + r;
        float bb = Wb[o];
        const float* xr = x   + (size_t)b * CC * NN + (size_t)o * NN + n0 + tx * 8;
        float*       yr = out + (size_t)b * CC * NN + (size_t)o * NN + n0 + tx * 8;
        float4 x0 = *(const float4*)xr;
        float4 x1 = *(const float4*)(xr + 4);
        *(float4*)yr = make_float4(acc[r][0] + bb + x0.x, acc[r][1] + bb + x0.y,
                                   acc[r][2] + bb + x0.z, acc[r][3] + bb + x0.w);
        *(float4*)(yr + 4) = make_float4(acc[r][4] + bb + x1.x, acc[r][5] + bb + x1.y,
                                         acc[r][6] + bb + x1.z, acc[r][7] + bb + x1.w);
    }
}

// ================= launch =================
extern "C" void kernel_launch(void* const* d_in, const int* in_sizes, int n_in,
                              void* d_out, int out_size) {
    const float* x  = (const float*)d_in[0];
    const float* tw = (const float*)d_in[1];
    const float* tb = (const float*)d_in[2];
    const float* pw = (const float*)d_in[3];
    const float* pb = (const float*)d_in[4];
    const float* gw = (const float*)d_in[5];
    const float* gb = (const float*)d_in[6];
    const float* Ww = (const float*)d_in[7];
    const float* Wb = (const float*)d_in[8];
    float* out = (float*)d_out;

    k0_init      <<<dim3(BB * NN / 256),              256>>>();
    k0x_split    <<<dim3(BB * CC * NN / 4 / 256),     256>>>(x);
    k0w_split    <<<dim3(3 * CC * CHH / 256),         256>>>(tw, pw, gw);
    k1_mma       <<<dim3(NN / 64, 3, BB),             256>>>(tb, pb, gb);
    k2_scores_mma<<<dim3(NN / 128, NN / 128, BB),     256>>>();
    k3_softmax   <<<dim3(BB * NN / 8),                256>>>();
    k4_av_fp16   <<<dim3(NN / 64, BB),                256>>>();
    k5_out       <<<dim3(NN / TILE, CC / TILE, BB),   256>>>(x, Ww, Wb, out);
}